// round 3
// baseline (speedup 1.0000x reference)
#include <cuda_runtime.h>
#include <cstdint>

#define BATCH 64
#define VOCAB 16000
#define EMBED 256
#define DIMH  512
#define G3    1536
#define TSTEPS 63
#define GAMMA 0.1f
#define VC    128
#define NPB   125   // pred blocks = VOCAB / VC

#define OUT_H_STRIDE (BATCH*DIMH)     // 32768
#define OUT_P_STRIDE (BATCH*VOCAB)    // 1024000
#define PRED_OFF (65*OUT_H_STRIDE)    // 2129920

// ---------------- scratch (device globals; no allocation) ----------------
__device__ float d_h[2][BATCH*DIMH];     // fp32 hidden state (ping-pong)
__device__ float d_ht[2][BATCH*DIMH];    // tf32-rounded hidden state
__device__ float d_xt[BATCH*EMBED];      // tf32-rounded soft embedding
__device__ float d_pE[NPB*BATCH*EMBED];  // partial E sums per vocab block
__device__ float d_pS[NPB*BATCH];        // partial softmax denominators
__device__ float d_outw_t[VOCAB*DIMH];   // tf32-rounded weights
__device__ float d_emb_t[VOCAB*EMBED];
__device__ float d_wih_t[G3*EMBED];
__device__ float d_whh_t[G3*DIMH];

// ---------------- helpers ----------------
__device__ __forceinline__ float to_tf32(float x) {
    unsigned u;
    asm("cvt.rna.tf32.f32 %0, %1;" : "=r"(u) : "f"(x));
    return __uint_as_float(u);
}

__device__ __forceinline__ void mma8(float* c,
                                     unsigned a0, unsigned a1, unsigned a2, unsigned a3,
                                     unsigned b0, unsigned b1) {
    asm volatile(
        "mma.sync.aligned.m16n8k8.row.col.f32.tf32.tf32.f32 "
        "{%0,%1,%2,%3}, {%4,%5,%6,%7}, {%8,%9}, {%0,%1,%2,%3};\n"
        : "+f"(c[0]), "+f"(c[1]), "+f"(c[2]), "+f"(c[3])
        : "r"(a0), "r"(a1), "r"(a2), "r"(a3), "r"(b0), "r"(b1));
}

// ---------------- prep: tf32-round all weights ----------------
__global__ void prep_kernel(const float* __restrict__ outw, const float* __restrict__ emb,
                            const float* __restrict__ wih,  const float* __restrict__ whh) {
    int64_t i = (int64_t)blockIdx.x * blockDim.x + threadIdx.x;
    int64_t stride = (int64_t)gridDim.x * blockDim.x;
    const int64_t N1 = (int64_t)VOCAB * DIMH;
    const int64_t N2 = N1 + (int64_t)VOCAB * EMBED;
    const int64_t N3 = N2 + (int64_t)G3 * EMBED;
    const int64_t N4 = N3 + (int64_t)G3 * DIMH;
    for (; i < N4; i += stride) {
        if (i < N1)       d_outw_t[i]      = to_tf32(outw[i]);
        else if (i < N2)  d_emb_t[i - N1]  = to_tf32(emb[i - N1]);
        else if (i < N3)  d_wih_t[i - N2]  = to_tf32(wih[i - N2]);
        else              d_whh_t[i - N3]  = to_tf32(whh[i - N3]);
    }
}

// ---------------- init: h0, x0, zero rows ----------------
__global__ void init_kernel(const float* __restrict__ z, const float* __restrict__ labels,
                            const float* __restrict__ emb, const float* __restrict__ fcw,
                            const float* __restrict__ fcb, float* __restrict__ out) {
    int64_t i = (int64_t)blockIdx.x * blockDim.x + threadIdx.x;
    int64_t stride = (int64_t)gridDim.x * blockDim.x;
    const int64_t NH0 = 32768;              // h0 -> outputs[0]
    const int64_t NZ  = 65536;              // outputs[1] = 0
    const int64_t NX  = 81920;              // x0 = emb[<sos>]
    const int64_t NP  = NX + (int64_t)OUT_P_STRIDE; // predictions[0] = 0
    for (; i < NP; i += stride) {
        if (i < NH0) {
            int b = (int)(i >> 9), j = (int)(i & 511);
            float v = (j < 64) ? (1.f - labels[b]) * fcw[j] + fcb[j]
                               : z[b * 448 + (j - 64)];
            d_h[0][i] = v; d_ht[0][i] = to_tf32(v); out[i] = v;
        } else if (i < NZ) {
            out[i] = 0.f;
        } else if (i < NX) {
            int l = (int)(i - NZ); int c = l & 255;
            d_xt[l] = to_tf32(emb[2 * EMBED + c]);   // IDX_SOS = 2
        } else {
            out[PRED_OFF + (i - NX)] = 0.f;
        }
    }
}

// ---------------- GRU cell: h_new = GRU(x, h) ----------------
__global__ __launch_bounds__(128) void gru_kernel(int cur,
        const float* __restrict__ bih, const float* __restrict__ bhh,
        float* __restrict__ outh) {
    const int nxt = cur ^ 1;
    const float* xt  = d_xt;
    const float* htp = d_ht[cur];
    const float* hp  = d_h[cur];
    float* hn  = d_h[nxt];
    float* htn = d_ht[nxt];

    int warp = threadIdx.x >> 5, lane = threadIdx.x & 31;
    int g = lane >> 2, tig = lane & 3;
    int j0 = blockIdx.x * 8;
    int m0 = warp * 16;

    float acc[6][4];
    #pragma unroll
    for (int a = 0; a < 6; a++)
        #pragma unroll
        for (int b = 0; b < 4; b++) acc[a][b] = 0.f;

    // gi = x @ w_ih^T  (K = 256)
    {
        const int r0 = (m0 + g) * EMBED, r1 = (m0 + g + 8) * EMBED;
        #pragma unroll 4
        for (int k8 = 0; k8 < 32; k8++) {
            int kb = k8 * 8 + tig;
            unsigned a0 = __float_as_uint(xt[r0 + kb]);
            unsigned a1 = __float_as_uint(xt[r1 + kb]);
            unsigned a2 = __float_as_uint(xt[r0 + kb + 4]);
            unsigned a3 = __float_as_uint(xt[r1 + kb + 4]);
            #pragma unroll
            for (int gate = 0; gate < 3; gate++) {
                int row = gate * DIMH + j0 + g;
                unsigned b0 = __float_as_uint(d_wih_t[row * EMBED + kb]);
                unsigned b1 = __float_as_uint(d_wih_t[row * EMBED + kb + 4]);
                mma8(acc[gate], a0, a1, a2, a3, b0, b1);
            }
        }
    }
    // gh = h @ w_hh^T  (K = 512)
    {
        const int s0 = (m0 + g) * DIMH, s1 = (m0 + g + 8) * DIMH;
        #pragma unroll 4
        for (int k8 = 0; k8 < 64; k8++) {
            int kb = k8 * 8 + tig;
            unsigned a0 = __float_as_uint(htp[s0 + kb]);
            unsigned a1 = __float_as_uint(htp[s1 + kb]);
            unsigned a2 = __float_as_uint(htp[s0 + kb + 4]);
            unsigned a3 = __float_as_uint(htp[s1 + kb + 4]);
            #pragma unroll
            for (int gate = 0; gate < 3; gate++) {
                int row = gate * DIMH + j0 + g;
                unsigned b0 = __float_as_uint(d_whh_t[row * DIMH + kb]);
                unsigned b1 = __float_as_uint(d_whh_t[row * DIMH + kb + 4]);
                mma8(acc[3 + gate], a0, a1, a2, a3, b0, b1);
            }
        }
    }
    // gates + state update
    #pragma unroll
    for (int idx = 0; idx < 4; idx++) {
        int m = m0 + g + ((idx & 2) ? 8 : 0);
        int n = 2 * tig + (idx & 1);
        int j = j0 + n;
        float ir  = acc[0][idx] + bih[j];            float hr = acc[3][idx] + bhh[j];
        float iz  = acc[1][idx] + bih[DIMH + j];     float hz = acc[4][idx] + bhh[DIMH + j];
        float inn = acc[2][idx] + bih[2*DIMH + j];   float hnn = acc[5][idx] + bhh[2*DIMH + j];
        float r  = 1.f / (1.f + expf(-(ir + hr)));
        float zg = 1.f / (1.f + expf(-(iz + hz)));
        float nn = tanhf(inn + r * hnn);
        float hv = (1.f - zg) * nn + zg * hp[m * DIMH + j];
        hn[m * DIMH + j]  = hv;
        htn[m * DIMH + j] = to_tf32(hv);
        outh[m * DIMH + j] = hv;
    }
}

// ---------------- pred + softmax partials per 128-vocab block ----------------
#define SMEM_BYTES 168960
__global__ __launch_bounds__(256, 1) void pred_kernel(int parity,
        const float* __restrict__ gum, const float* __restrict__ outb,
        float* __restrict__ predout) {
    extern __shared__ float sm[];
    const float* ht = d_ht[parity];
    int tid = threadIdx.x;
    int warp = tid >> 5, lane = tid & 31;
    int g = lane >> 2, tig = lane & 3;
    int v0 = blockIdx.x * VC;

    // ---- phase 0: stage h (64 x 512, padded to 516) ----
    float* sH = sm;              // [64][516]
    float* sW = sm + 64 * 516;   // [128][36]
    for (int idx = tid; idx < BATCH * DIMH; idx += 256)
        sH[(idx >> 9) * 516 + (idx & 511)] = ht[idx];

    // ---- phase 1: pred = h @ out_w^T for this vocab chunk ----
    int mt = warp & 3, m0 = mt * 16;
    int nb = (warp >> 2) * 64;
    float pacc[8][4];
    #pragma unroll
    for (int a = 0; a < 8; a++)
        #pragma unroll
        for (int b = 0; b < 4; b++) pacc[a][b] = 0.f;

    for (int kc = 0; kc < 16; kc++) {
        __syncthreads();
        #pragma unroll
        for (int l = 0; l < 16; l++) {
            int idx = tid + l * 256;          // 128*32 elems
            int vl = idx >> 5, kl = idx & 31;
            sW[vl * 36 + kl] = d_outw_t[(v0 + vl) * DIMH + kc * 32 + kl];
        }
        __syncthreads();
        #pragma unroll
        for (int k8 = 0; k8 < 4; k8++) {
            int kk = kc * 32 + k8 * 8 + tig;
            unsigned a0 = __float_as_uint(sH[(m0 + g) * 516 + kk]);
            unsigned a1 = __float_as_uint(sH[(m0 + g + 8) * 516 + kk]);
            unsigned a2 = __float_as_uint(sH[(m0 + g) * 516 + kk + 4]);
            unsigned a3 = __float_as_uint(sH[(m0 + g + 8) * 516 + kk + 4]);
            #pragma unroll
            for (int nt = 0; nt < 8; nt++) {
                int vl = nb + nt * 8 + g;
                unsigned b0 = __float_as_uint(sW[vl * 36 + k8 * 8 + tig]);
                unsigned b1 = __float_as_uint(sW[vl * 36 + k8 * 8 + tig + 4]);
                mma8(pacc[nt], a0, a1, a2, a3, b0, b1);
            }
        }
    }

    // ---- epilogue 1: write pred, compute e = exp(pred + gumbel) ----
    #pragma unroll
    for (int nt = 0; nt < 8; nt++) {
        int vcol = nb + nt * 8 + 2 * tig;
        int vg = v0 + vcol;
        float ob0 = outb[vg], ob1 = outb[vg + 1];
        int rA = m0 + g, rB = m0 + g + 8;
        float p00 = pacc[nt][0] + ob0, p01 = pacc[nt][1] + ob1;
        float p10 = pacc[nt][2] + ob0, p11 = pacc[nt][3] + ob1;
        *(float2*)&predout[rA * VOCAB + vg] = make_float2(p00, p01);
        *(float2*)&predout[rB * VOCAB + vg] = make_float2(p10, p11);
        float2 gA = *(const float2*)&gum[rA * VOCAB + vg];
        float2 gB = *(const float2*)&gum[rB * VOCAB + vg];
        pacc[nt][0] = __expf(p00 + gA.x); pacc[nt][1] = __expf(p01 + gA.y);
        pacc[nt][2] = __expf(p10 + gB.x); pacc[nt][3] = __expf(p11 + gB.y);
    }
    __syncthreads();   // done reading sH / sW — SMEM is repurposed below

    float* sE   = sm;             // [64][132]
    float* sEmb = sm + 64 * 132;  // [128][264]
    #pragma unroll
    for (int nt = 0; nt < 8; nt++) {
        int vcol = nb + nt * 8 + 2 * tig;
        *(float2*)&sE[(m0 + g) * 132 + vcol] =
            make_float2(to_tf32(pacc[nt][0]), to_tf32(pacc[nt][1]));
        *(float2*)&sE[(m0 + g + 8) * 132 + vcol] =
            make_float2(to_tf32(pacc[nt][2]), to_tf32(pacc[nt][3]));
    }
    for (int idx = tid; idx < VC * EMBED; idx += 256) {
        int vl = idx >> 8, c = idx & 255;
        sEmb[vl * 264 + c] = d_emb_t[(v0 + vl) * EMBED + c];
    }
    __syncthreads();

    // partial softmax denominator
    if (tid < BATCH) {
        float s = 0.f;
        #pragma unroll 8
        for (int k = 0; k < VC; k++) s += sE[tid * 132 + k];
        d_pS[blockIdx.x * BATCH + tid] = s;
    }

    // ---- phase 3: partial E = e @ emb_chunk (64 x 256, K=128) ----
    int nbE = (warp >> 2) * 128;
    float eacc[16][4];
    #pragma unroll
    for (int a = 0; a < 16; a++)
        #pragma unroll
        for (int b = 0; b < 4; b++) eacc[a][b] = 0.f;

    #pragma unroll
    for (int k8 = 0; k8 < 16; k8++) {
        int kk = k8 * 8 + tig;
        unsigned a0 = __float_as_uint(sE[(m0 + g) * 132 + kk]);
        unsigned a1 = __float_as_uint(sE[(m0 + g + 8) * 132 + kk]);
        unsigned a2 = __float_as_uint(sE[(m0 + g) * 132 + kk + 4]);
        unsigned a3 = __float_as_uint(sE[(m0 + g + 8) * 132 + kk + 4]);
        #pragma unroll
        for (int nt = 0; nt < 16; nt++) {
            int nc = nbE + nt * 8 + g;
            unsigned b0 = __float_as_uint(sEmb[kk * 264 + nc]);
            unsigned b1 = __float_as_uint(sEmb[(kk + 4) * 264 + nc]);
            mma8(eacc[nt], a0, a1, a2, a3, b0, b1);
        }
    }
    float* pEblk = d_pE + blockIdx.x * (BATCH * EMBED);
    #pragma unroll
    for (int nt = 0; nt < 16; nt++) {
        int c = nbE + nt * 8 + 2 * tig;
        *(float2*)&pEblk[(m0 + g) * EMBED + c] = make_float2(eacc[nt][0], eacc[nt][1]);
        *(float2*)&pEblk[(m0 + g + 8) * EMBED + c] = make_float2(eacc[nt][2], eacc[nt][3]);
    }
}

// ---------------- reduce partials -> x_next ----------------
__global__ __launch_bounds__(256) void reduce_kernel() {
    __shared__ float sbuf[128];
    __shared__ float ssinv;
    int b = blockIdx.x, tid = threadIdx.x;
    if (tid < 128) sbuf[tid] = (tid < NPB) ? d_pS[tid * BATCH + b] : 0.f;
    __syncthreads();
    if (tid == 0) {
        float s = 0.f;
        for (int k = 0; k < NPB; k++) s += sbuf[k];
        ssinv = 1.f / (GAMMA * s);
    }
    __syncthreads();
    float sinv = ssinv;
    float acc = 0.f;
    const float* p = d_pE + b * EMBED + tid;
    #pragma unroll 5
    for (int k = 0; k < NPB; k++) acc += p[k * (BATCH * EMBED)];
    d_xt[b * EMBED + tid] = to_tf32(acc * sinv);
}

// ---------------- launch ----------------
extern "C" void kernel_launch(void* const* d_in, const int* in_sizes, int n_in,
                              void* d_out, int out_size) {
    const float* z      = (const float*)d_in[0];
    const float* labels = (const float*)d_in[1];
    // d_in[2] src, d_in[3] src_len: unused by the transfered=True path
    const float* gum    = (const float*)d_in[4];
    const float* emb    = (const float*)d_in[5];
    const float* fcw    = (const float*)d_in[6];
    const float* fcb    = (const float*)d_in[7];
    const float* wih    = (const float*)d_in[8];
    const float* whh    = (const float*)d_in[9];
    const float* bih    = (const float*)d_in[10];
    const float* bhh    = (const float*)d_in[11];
    const float* outw   = (const float*)d_in[12];
    const float* outb   = (const float*)d_in[13];
    float* out = (float*)d_out;

    cudaFuncSetAttribute(pred_kernel, cudaFuncAttributeMaxDynamicSharedMemorySize, SMEM_BYTES);

    prep_kernel<<<1024, 256>>>(outw, emb, wih, whh);
    init_kernel<<<1024, 256>>>(z, labels, emb, fcw, fcb, out);

    for (int i = 0; i < TSTEPS; i++) {
        int cur = i & 1, nxt = cur ^ 1;
        gru_kernel<<<64, 128>>>(cur, bih, bhh, out + (int64_t)(2 + i) * OUT_H_STRIDE);
        pred_kernel<<<NPB, 256, SMEM_BYTES>>>(nxt, gum + (int64_t)i * OUT_P_STRIDE,
                                              outb, out + PRED_OFF + (int64_t)(i + 1) * OUT_P_STRIDE);
        if (i < TSTEPS - 1) reduce_kernel<<<BATCH, 256>>>();
    }
}

// round 4
// speedup vs baseline: 1.2634x; 1.2634x over previous
#include <cuda_runtime.h>
#include <cstdint>

#define BATCH 64
#define VOCAB 16000
#define EMBED 256
#define DIMH  512
#define G3    1536
#define TSTEPS 63
#define GAMMA 0.1f
#define VC    128
#define NPB   125   // pred blocks = VOCAB / VC

#define OUT_H_STRIDE (BATCH*DIMH)     // 32768
#define OUT_P_STRIDE (BATCH*VOCAB)    // 1024000
#define PRED_OFF (65*OUT_H_STRIDE)    // 2129920

// ---------------- scratch (device globals; no allocation) ----------------
__device__ __align__(16) float d_h[2][BATCH*DIMH];      // fp32 hidden state (row-major, ping-pong)
__device__ __align__(16) float d_hfrag[2][BATCH*DIMH];  // tf32 hidden state in A-fragment layout [mt4][k8_64][lane32][4]
__device__ __align__(16) float d_xfrag[BATCH*EMBED];    // tf32 soft embedding, A-fragment layout [mt4][k8_32][lane32][4]
__device__ __align__(16) float d_pE[NPB*BATCH*EMBED];   // partial E sums per vocab block
__device__ float d_pS[NPB*BATCH];                       // partial softmax denominators
// B-operand fragment layouts (precomputed once, tf32-rounded)
__device__ __align__(16) float d_outwf[VOCAB*DIMH];   // [vb125][nh2][nt8][kp32][lane32][4]
__device__ __align__(16) float d_embf[VOCAB*EMBED];   // [vb125][nh2][nt16][kp8][lane32][4]
__device__ __align__(16) float d_wihf[G3*EMBED];      // [gate3][jb64][kp16][lane32][4]
__device__ __align__(16) float d_whhf[G3*DIMH];       // [gate3][jb64][kp32][lane32][4]

// ---------------- helpers ----------------
__device__ __forceinline__ float to_tf32(float x) {
    unsigned u;
    asm("cvt.rna.tf32.f32 %0, %1;" : "=r"(u) : "f"(x));
    return __uint_as_float(u);
}

__device__ __forceinline__ void mma8(float* c, float4 a, float b0, float b1) {
    asm volatile(
        "mma.sync.aligned.m16n8k8.row.col.f32.tf32.tf32.f32 "
        "{%0,%1,%2,%3}, {%4,%5,%6,%7}, {%8,%9}, {%0,%1,%2,%3};\n"
        : "+f"(c[0]), "+f"(c[1]), "+f"(c[2]), "+f"(c[3])
        : "r"(__float_as_uint(a.x)), "r"(__float_as_uint(a.y)),
          "r"(__float_as_uint(a.z)), "r"(__float_as_uint(a.w)),
          "r"(__float_as_uint(b0)), "r"(__float_as_uint(b1)));
}

// A-fragment scatter position: value at (row m in 0..63, col k), k8 = k>>3
// lane = (mr&7)*4 + (kc&3), slot = (kc>=4 ? 2:0) + (mr>=8 ? 1:0)
__device__ __forceinline__ int frag_idx(int m, int k, int k8dim) {
    int mr = m & 15, kc = k & 7, k8 = k >> 3, mt = m >> 4;
    int lane = ((mr & 7) << 2) | (kc & 3);
    int slot = ((kc >= 4) ? 2 : 0) | ((mr >= 8) ? 1 : 0);
    return ((mt * k8dim + k8) * 32 + lane) * 4 + slot;
}

// ---------------- prep: build tf32 fragment-layout weights ----------------
__global__ void prep_kernel(const float* __restrict__ outw, const float* __restrict__ emb,
                            const float* __restrict__ wih,  const float* __restrict__ whh) {
    const int T1 = VOCAB*DIMH/4;            // 2048000
    const int T2 = T1 + VOCAB*EMBED/4;      // +1024000
    const int T3 = T2 + G3*EMBED/4;         // +98304
    const int T4 = T3 + G3*DIMH/4;          // +196608
    for (int gid = blockIdx.x * blockDim.x + threadIdx.x; gid < T4;
         gid += gridDim.x * blockDim.x) {
        if (gid < T1) {
            int lane = gid & 31, kp = (gid >> 5) & 31, nt = (gid >> 10) & 7;
            int nh = (gid >> 13) & 1, vb = gid >> 14;
            int g = lane >> 2, tig = lane & 3;
            int n = vb * 128 + nh * 64 + nt * 8 + g;
            const float* r = outw + n * DIMH + kp * 16 + tig;
            float4 q = make_float4(to_tf32(r[0]), to_tf32(r[4]), to_tf32(r[8]), to_tf32(r[12]));
            ((float4*)d_outwf)[gid] = q;
        } else if (gid < T2) {
            int id = gid - T1;
            int lane = id & 31, kp = (id >> 5) & 7, nt = (id >> 8) & 15;
            int nh = (id >> 12) & 1, vb = id >> 13;
            int g = lane >> 2, tig = lane & 3;
            int n = nh * 128 + nt * 8 + g;
            int k0 = vb * 128 + kp * 16 + tig;
            float4 q = make_float4(to_tf32(emb[(int64_t)k0 * EMBED + n]),
                                   to_tf32(emb[(int64_t)(k0 + 4) * EMBED + n]),
                                   to_tf32(emb[(int64_t)(k0 + 8) * EMBED + n]),
                                   to_tf32(emb[(int64_t)(k0 + 12) * EMBED + n]));
            ((float4*)d_embf)[id] = q;
        } else if (gid < T3) {
            int id = gid - T2;
            int lane = id & 31, kp = (id >> 5) & 15, jb = (id >> 9) & 63, gate = id >> 15;
            int g = lane >> 2, tig = lane & 3;
            int row = gate * DIMH + jb * 8 + g;
            const float* r = wih + row * EMBED + kp * 16 + tig;
            float4 q = make_float4(to_tf32(r[0]), to_tf32(r[4]), to_tf32(r[8]), to_tf32(r[12]));
            ((float4*)d_wihf)[id] = q;
        } else {
            int id = gid - T3;
            int lane = id & 31, kp = (id >> 5) & 31, jb = (id >> 10) & 63, gate = id >> 16;
            int g = lane >> 2, tig = lane & 3;
            int row = gate * DIMH + jb * 8 + g;
            const float* r = whh + row * DIMH + kp * 16 + tig;
            float4 q = make_float4(to_tf32(r[0]), to_tf32(r[4]), to_tf32(r[8]), to_tf32(r[12]));
            ((float4*)d_whhf)[id] = q;
        }
    }
}

// ---------------- init: h0, x0, zero rows ----------------
__global__ void init_kernel(const float* __restrict__ z, const float* __restrict__ labels,
                            const float* __restrict__ emb, const float* __restrict__ fcw,
                            const float* __restrict__ fcb, float* __restrict__ out) {
    int64_t i = (int64_t)blockIdx.x * blockDim.x + threadIdx.x;
    int64_t stride = (int64_t)gridDim.x * blockDim.x;
    const int64_t NH0 = 32768;              // h0 -> outputs[0] + state
    const int64_t NZ  = 65536;              // outputs[1] = 0
    const int64_t NX  = 81920;              // x0 = emb[<sos>]
    const int64_t NP  = NX + (int64_t)OUT_P_STRIDE; // predictions[0] = 0
    for (; i < NP; i += stride) {
        if (i < NH0) {
            int b = (int)(i >> 9), j = (int)(i & 511);
            float v = (j < 64) ? (1.f - labels[b]) * fcw[j] + fcb[j]
                               : z[b * 448 + (j - 64)];
            d_h[0][i] = v; out[i] = v;
            d_hfrag[0][frag_idx(b, j, 64)] = to_tf32(v);
        } else if (i < NZ) {
            out[i] = 0.f;
        } else if (i < NX) {
            int l = (int)(i - NZ); int b = l >> 8, c = l & 255;
            d_xfrag[frag_idx(b, c, 32)] = to_tf32(emb[2 * EMBED + c]);   // IDX_SOS = 2
        } else {
            out[PRED_OFF + (i - NX)] = 0.f;
        }
    }
}

// ---------------- GRU cell: h_new = GRU(x, h) ----------------
__global__ __launch_bounds__(128) void gru_kernel(int cur,
        const float* __restrict__ bih, const float* __restrict__ bhh,
        float* __restrict__ outh) {
    const int nxt = cur ^ 1;
    int tid = threadIdx.x, lane = tid & 31, mt = tid >> 5;
    int g = lane >> 2, tig = lane & 3;
    int jb = blockIdx.x;            // 8 output cols j0 = jb*8
    int j0 = jb * 8;
    int m0 = mt * 16;

    float acc[6][4];
    #pragma unroll
    for (int a = 0; a < 6; a++)
        #pragma unroll
        for (int b = 0; b < 4; b++) acc[a][b] = 0.f;

    const float4* Ax = (const float4*)d_xfrag + mt * 32 * 32 + lane;
    const float4* Ah = (const float4*)d_hfrag[cur] + mt * 64 * 32 + lane;
    const float4* Bi = (const float4*)d_wihf + jb * 16 * 32 + lane;  // + gate*64*16*32 + kp*32
    const float4* Bh = (const float4*)d_whhf + jb * 32 * 32 + lane;  // + gate*64*32*32 + kp*32

    // gi = x @ w_ih^T  (K = 256 -> 16 kp)
    #pragma unroll 2
    for (int kp = 0; kp < 16; kp++) {
        float4 a0 = Ax[(2 * kp) * 32];
        float4 a1 = Ax[(2 * kp + 1) * 32];
        #pragma unroll
        for (int gate = 0; gate < 3; gate++) {
            float4 b = Bi[gate * (64 * 16 * 32) + kp * 32];
            mma8(acc[gate], a0, b.x, b.y);
            mma8(acc[gate], a1, b.z, b.w);
        }
    }
    // gh = h @ w_hh^T  (K = 512 -> 32 kp)
    #pragma unroll 2
    for (int kp = 0; kp < 32; kp++) {
        float4 a0 = Ah[(2 * kp) * 32];
        float4 a1 = Ah[(2 * kp + 1) * 32];
        #pragma unroll
        for (int gate = 0; gate < 3; gate++) {
            float4 b = Bh[gate * (64 * 32 * 32) + kp * 32];
            mma8(acc[3 + gate], a0, b.x, b.y);
            mma8(acc[3 + gate], a1, b.z, b.w);
        }
    }
    // gates + state update
    const float* hp = d_h[cur];
    float* hn = d_h[nxt];
    float* hf = d_hfrag[nxt];
    #pragma unroll
    for (int idx = 0; idx < 4; idx++) {
        int m = m0 + g + ((idx & 2) ? 8 : 0);
        int j = j0 + 2 * tig + (idx & 1);
        float ir  = acc[0][idx] + bih[j];            float hr  = acc[3][idx] + bhh[j];
        float iz  = acc[1][idx] + bih[DIMH + j];     float hz  = acc[4][idx] + bhh[DIMH + j];
        float inn = acc[2][idx] + bih[2*DIMH + j];   float hnn = acc[5][idx] + bhh[2*DIMH + j];
        float r  = 1.f / (1.f + expf(-(ir + hr)));
        float zg = 1.f / (1.f + expf(-(iz + hz)));
        float nn = tanhf(inn + r * hnn);
        float hv = (1.f - zg) * nn + zg * hp[m * DIMH + j];
        hn[m * DIMH + j] = hv;
        outh[m * DIMH + j] = hv;
        hf[frag_idx(m, j, 64)] = to_tf32(hv);
    }
}

// ---------------- pred + softmax partials per 128-vocab block ----------------
__global__ __launch_bounds__(256) void pred_kernel(int parity,
        const float* __restrict__ gum, const float* __restrict__ outb,
        float* __restrict__ predout) {
    __shared__ __align__(16) float sEf[4 * 16 * 32 * 4];   // e in A-fragment layout, 32KB
    __shared__ float sS[64];
    int tid = threadIdx.x, lane = tid & 31, warp = tid >> 5;
    int g = lane >> 2, tig = lane & 3;
    int mt = warp & 3, nh = warp >> 2;
    int vb = blockIdx.x;

    if (tid < 64) sS[tid] = 0.f;
    __syncthreads();

    // ---- phase 1: pred = h @ out_w^T  (M=64, N=128, K=512) ----
    float pacc[8][4];
    #pragma unroll
    for (int a = 0; a < 8; a++)
        #pragma unroll
        for (int b = 0; b < 4; b++) pacc[a][b] = 0.f;

    const float4* Af = (const float4*)d_hfrag[parity] + mt * 64 * 32 + lane;
    const float4* Bf = (const float4*)d_outwf + (vb * 2 + nh) * (8 * 32 * 32) + lane;
    #pragma unroll 2
    for (int kp = 0; kp < 32; kp++) {
        float4 a0 = Af[(2 * kp) * 32];
        float4 a1 = Af[(2 * kp + 1) * 32];
        #pragma unroll
        for (int nt = 0; nt < 8; nt++) {
            float4 b = Bf[(nt * 32 + kp) * 32];
            mma8(pacc[nt], a0, b.x, b.y);
            mma8(pacc[nt], a1, b.z, b.w);
        }
    }

    // ---- epilogue: write pred, e = exp(pred + gumbel), stash e-frags + row sums ----
    int rA = mt * 16 + g, rB = rA + 8;
    float slo = 0.f, shi = 0.f;
    #pragma unroll
    for (int nt = 0; nt < 8; nt++) {
        int vcol = nh * 64 + nt * 8 + 2 * tig;
        int vg = vb * 128 + vcol;
        float ob0 = outb[vg], ob1 = outb[vg + 1];
        float p00 = pacc[nt][0] + ob0, p01 = pacc[nt][1] + ob1;
        float p10 = pacc[nt][2] + ob0, p11 = pacc[nt][3] + ob1;
        *(float2*)&predout[rA * VOCAB + vg] = make_float2(p00, p01);
        *(float2*)&predout[rB * VOCAB + vg] = make_float2(p10, p11);
        float2 gA = *(const float2*)&gum[rA * VOCAB + vg];
        float2 gB = *(const float2*)&gum[rB * VOCAB + vg];
        float e00 = __expf(p00 + gA.x), e01 = __expf(p01 + gA.y);
        float e10 = __expf(p10 + gB.x), e11 = __expf(p11 + gB.y);
        slo += e00 + e01; shi += e10 + e11;
        // scatter into fragment layout (k8 dim = 16 for K=128)
        int k8 = nh * 8 + nt;
        int kc0 = 2 * tig, kc1 = 2 * tig + 1;
        int lane0 = ((g) << 2) | (kc0 & 3), slot0h = (kc0 >= 4) ? 2 : 0;
        int lane1 = ((g) << 2) | (kc1 & 3), slot1h = (kc1 >= 4) ? 2 : 0;
        float* baseA0 = &sEf[((mt * 16 + k8) * 32 + lane0) * 4];
        float* baseA1 = &sEf[((mt * 16 + k8) * 32 + lane1) * 4];
        baseA0[slot0h + 0] = to_tf32(e00);
        baseA1[slot1h + 0] = to_tf32(e01);
        baseA0[slot0h + 1] = to_tf32(e10);
        baseA1[slot1h + 1] = to_tf32(e11);
    }
    slo += __shfl_down_sync(0xffffffffu, slo, 1);
    slo += __shfl_down_sync(0xffffffffu, slo, 2);
    shi += __shfl_down_sync(0xffffffffu, shi, 1);
    shi += __shfl_down_sync(0xffffffffu, shi, 2);
    if (tig == 0) {
        atomicAdd(&sS[rA], slo);
        atomicAdd(&sS[rB], shi);
    }
    __syncthreads();
    if (tid < 64) d_pS[vb * 64 + tid] = sS[tid];

    // ---- phase 3: partial E = e @ emb_chunk  (M=64, N=256, K=128) ----
    const float4* sE4 = (const float4*)sEf + mt * 16 * 32 + lane;
    const float4* Ef = (const float4*)d_embf + (vb * 2 + nh) * (16 * 8 * 32) + lane;
    float* pEblk = d_pE + vb * (BATCH * EMBED);
    #pragma unroll
    for (int half = 0; half < 2; half++) {
        float eacc[8][4];
        #pragma unroll
        for (int a = 0; a < 8; a++)
            #pragma unroll
            for (int b = 0; b < 4; b++) eacc[a][b] = 0.f;
        #pragma unroll 2
        for (int kp = 0; kp < 8; kp++) {
            float4 a0 = sE4[(2 * kp) * 32];
            float4 a1 = sE4[(2 * kp + 1) * 32];
            #pragma unroll
            for (int t = 0; t < 8; t++) {
                float4 b = Ef[((half * 8 + t) * 8 + kp) * 32];
                mma8(eacc[t], a0, b.x, b.y);
                mma8(eacc[t], a1, b.z, b.w);
            }
        }
        #pragma unroll
        for (int t = 0; t < 8; t++) {
            int c = nh * 128 + (half * 8 + t) * 8 + 2 * tig;
            *(float2*)&pEblk[rA * EMBED + c] = make_float2(eacc[t][0], eacc[t][1]);
            *(float2*)&pEblk[rB * EMBED + c] = make_float2(eacc[t][2], eacc[t][3]);
        }
    }
}

// ---------------- reduce partials -> x_next (fragment layout) ----------------
__global__ __launch_bounds__(256) void reduce_kernel() {
    __shared__ float sbuf[NPB];
    __shared__ float ssinv;
    int b = blockIdx.x, tid = threadIdx.x;
    if (tid < NPB) sbuf[tid] = d_pS[tid * 64 + b];
    __syncthreads();
    if (tid == 0) {
        float s = 0.f;
        for (int k = 0; k < NPB; k++) s += sbuf[k];
        ssinv = 1.f / (GAMMA * s);
    }
    __syncthreads();
    float sinv = ssinv;
    float acc = 0.f;
    const float* p = d_pE + b * EMBED + tid;
    #pragma unroll 5
    for (int k = 0; k < NPB; k++) acc += p[k * (BATCH * EMBED)];
    d_xfrag[frag_idx(b, tid, 32)] = to_tf32(acc * sinv);
}

// ---------------- launch ----------------
extern "C" void kernel_launch(void* const* d_in, const int* in_sizes, int n_in,
                              void* d_out, int out_size) {
    const float* z      = (const float*)d_in[0];
    const float* labels = (const float*)d_in[1];
    // d_in[2] src, d_in[3] src_len: unused by the transfered=True path
    const float* gum    = (const float*)d_in[4];
    const float* emb    = (const float*)d_in[5];
    const float* fcw    = (const float*)d_in[6];
    const float* fcb    = (const float*)d_in[7];
    const float* wih    = (const float*)d_in[8];
    const float* whh    = (const float*)d_in[9];
    const float* bih    = (const float*)d_in[10];
    const float* bhh    = (const float*)d_in[11];
    const float* outw   = (const float*)d_in[12];
    const float* outb   = (const float*)d_in[13];
    float* out = (float*)d_out;

    prep_kernel<<<2048, 256>>>(outw, emb, wih, whh);
    init_kernel<<<1024, 256>>>(z, labels, emb, fcw, fcb, out);

    for (int i = 0; i < TSTEPS; i++) {
        int cur = i & 1, nxt = cur ^ 1;
        gru_kernel<<<64, 128>>>(cur, bih, bhh, out + (int64_t)(2 + i) * OUT_H_STRIDE);
        pred_kernel<<<NPB, 256>>>(nxt, gum + (int64_t)i * OUT_P_STRIDE,
                                  outb, out + PRED_OFF + (int64_t)(i + 1) * OUT_P_STRIDE);
        if (i < TSTEPS - 1) reduce_kernel<<<64, 256>>>();
    }
}

// round 5
// speedup vs baseline: 2.0295x; 1.6063x over previous
#include <cuda_runtime.h>
#include <cstdint>

#define BATCH 64
#define VOCAB 16000
#define EMBED 256
#define DIMH  512
#define G3    1536
#define TSTEPS 63
#define GAMMA 0.1f
#define VC    128
#define NPB   125   // pred blocks = VOCAB / VC

#define OUT_H_STRIDE (BATCH*DIMH)     // 32768
#define OUT_P_STRIDE (BATCH*VOCAB)    // 1024000
#define PRED_OFF (65*OUT_H_STRIDE)    // 2129920

// ---------------- scratch (device globals; no allocation) ----------------
__device__ __align__(16) float d_h[2][BATCH*DIMH];      // fp32 hidden state (row-major, ping-pong)
__device__ __align__(16) float d_hfrag[2][BATCH*DIMH];  // tf32 hidden state, A-fragment layout [mt4][k8_64][lane32][4]
__device__ __align__(16) float d_xfrag[BATCH*EMBED];    // tf32 soft embedding, A-fragment layout [mt4][k8_32][lane32][4]
__device__ __align__(16) float d_pE[NPB*BATCH*EMBED];   // partial E sums per vocab block
__device__ float d_pS[NPB*BATCH];                       // partial softmax denominators
// B-operand fragment layouts (precomputed once, tf32-rounded)
__device__ __align__(16) float d_outwf[VOCAB*DIMH];   // [vb125][nh2][nt8][kp32][lane32][4]
__device__ __align__(16) float d_embf[VOCAB*EMBED];   // [vb125][nh2][nt16][kp8][lane32][4]
__device__ __align__(16) float d_wihf[G3*EMBED];      // [gate3][jb64][kp16][lane32][4]
__device__ __align__(16) float d_whhf[G3*DIMH];       // [gate3][jb64][kp32][lane32][4]

// ---------------- helpers ----------------
__device__ __forceinline__ float to_tf32(float x) {
    unsigned u;
    asm("cvt.rna.tf32.f32 %0, %1;" : "=r"(u) : "f"(x));
    return __uint_as_float(u);
}

__device__ __forceinline__ void mma8(float* c, float4 a, float b0, float b1) {
    asm volatile(
        "mma.sync.aligned.m16n8k8.row.col.f32.tf32.tf32.f32 "
        "{%0,%1,%2,%3}, {%4,%5,%6,%7}, {%8,%9}, {%0,%1,%2,%3};\n"
        : "+f"(c[0]), "+f"(c[1]), "+f"(c[2]), "+f"(c[3])
        : "r"(__float_as_uint(a.x)), "r"(__float_as_uint(a.y)),
          "r"(__float_as_uint(a.z)), "r"(__float_as_uint(a.w)),
          "r"(__float_as_uint(b0)), "r"(__float_as_uint(b1)));
}

// A-fragment scatter position for value at (row m in 0..63, col k)
__device__ __forceinline__ int frag_idx(int m, int k, int k8dim) {
    int mr = m & 15, kc = k & 7, k8 = k >> 3, mt = m >> 4;
    int lane = ((mr & 7) << 2) | (kc & 3);
    int slot = ((kc >= 4) ? 2 : 0) | ((mr >= 8) ? 1 : 0);
    return ((mt * k8dim + k8) * 32 + lane) * 4 + slot;
}

// ---------------- prep: build tf32 fragment-layout weights ----------------
__global__ void prep_kernel(const float* __restrict__ outw, const float* __restrict__ emb,
                            const float* __restrict__ wih,  const float* __restrict__ whh) {
    const int T1 = VOCAB*DIMH/4;            // 2048000
    const int T2 = T1 + VOCAB*EMBED/4;      // +1024000
    const int T3 = T2 + G3*EMBED/4;         // +98304
    const int T4 = T3 + G3*DIMH/4;          // +196608
    for (int gid = blockIdx.x * blockDim.x + threadIdx.x; gid < T4;
         gid += gridDim.x * blockDim.x) {
        if (gid < T1) {
            int lane = gid & 31, kp = (gid >> 5) & 31, nt = (gid >> 10) & 7;
            int nh = (gid >> 13) & 1, vb = gid >> 14;
            int g = lane >> 2, tig = lane & 3;
            int n = vb * 128 + nh * 64 + nt * 8 + g;
            const float* r = outw + n * DIMH + kp * 16 + tig;
            float4 q = make_float4(to_tf32(r[0]), to_tf32(r[4]), to_tf32(r[8]), to_tf32(r[12]));
            ((float4*)d_outwf)[gid] = q;
        } else if (gid < T2) {
            int id = gid - T1;
            int lane = id & 31, kp = (id >> 5) & 7, nt = (id >> 8) & 15;
            int nh = (id >> 12) & 1, vb = id >> 13;
            int g = lane >> 2, tig = lane & 3;
            int n = nh * 128 + nt * 8 + g;
            int k0 = vb * 128 + kp * 16 + tig;
            float4 q = make_float4(to_tf32(emb[(int64_t)k0 * EMBED + n]),
                                   to_tf32(emb[(int64_t)(k0 + 4) * EMBED + n]),
                                   to_tf32(emb[(int64_t)(k0 + 8) * EMBED + n]),
                                   to_tf32(emb[(int64_t)(k0 + 12) * EMBED + n]));
            ((float4*)d_embf)[id] = q;
        } else if (gid < T3) {
            int id = gid - T2;
            int lane = id & 31, kp = (id >> 5) & 15, jb = (id >> 9) & 63, gate = id >> 15;
            int g = lane >> 2, tig = lane & 3;
            int row = gate * DIMH + jb * 8 + g;
            const float* r = wih + row * EMBED + kp * 16 + tig;
            float4 q = make_float4(to_tf32(r[0]), to_tf32(r[4]), to_tf32(r[8]), to_tf32(r[12]));
            ((float4*)d_wihf)[id] = q;
        } else {
            int id = gid - T3;
            int lane = id & 31, kp = (id >> 5) & 31, jb = (id >> 10) & 63, gate = id >> 16;
            int g = lane >> 2, tig = lane & 3;
            int row = gate * DIMH + jb * 8 + g;
            const float* r = whh + row * DIMH + kp * 16 + tig;
            float4 q = make_float4(to_tf32(r[0]), to_tf32(r[4]), to_tf32(r[8]), to_tf32(r[12]));
            ((float4*)d_whhf)[id] = q;
        }
    }
}

// ---------------- init: h0, x0, zero rows ----------------
__global__ void init_kernel(const float* __restrict__ z, const float* __restrict__ labels,
                            const float* __restrict__ emb, const float* __restrict__ fcw,
                            const float* __restrict__ fcb, float* __restrict__ out) {
    int64_t i = (int64_t)blockIdx.x * blockDim.x + threadIdx.x;
    int64_t stride = (int64_t)gridDim.x * blockDim.x;
    const int64_t NH0 = 32768;              // h0 -> outputs[0] + state
    const int64_t NZ  = 65536;              // outputs[1] = 0
    const int64_t NX  = 81920;              // x0 = emb[<sos>]
    const int64_t NP  = NX + (int64_t)OUT_P_STRIDE; // predictions[0] = 0
    for (; i < NP; i += stride) {
        if (i < NH0) {
            int b = (int)(i >> 9), j = (int)(i & 511);
            float v = (j < 64) ? (1.f - labels[b]) * fcw[j] + fcb[j]
                               : z[b * 448 + (j - 64)];
            d_h[0][i] = v; out[i] = v;
            d_hfrag[0][frag_idx(b, j, 64)] = to_tf32(v);
        } else if (i < NZ) {
            out[i] = 0.f;
        } else if (i < NX) {
            int l = (int)(i - NZ); int b = l >> 8, c = l & 255;
            d_xfrag[frag_idx(b, c, 32)] = to_tf32(emb[2 * EMBED + c]);   // IDX_SOS = 2
        } else {
            out[PRED_OFF + (i - NX)] = 0.f;
        }
    }
}

// ---------------- GRU cell: h_new = GRU(x, h) ----------------
__global__ __launch_bounds__(128) void gru_kernel(int cur,
        const float* __restrict__ bih, const float* __restrict__ bhh,
        float* __restrict__ outh) {
    const int nxt = cur ^ 1;
    int tid = threadIdx.x, lane = tid & 31, mt = tid >> 5;
    int g = lane >> 2, tig = lane & 3;
    int jb = blockIdx.x;
    int j0 = jb * 8;
    int m0 = mt * 16;

    float acc[6][4];
    #pragma unroll
    for (int a = 0; a < 6; a++)
        #pragma unroll
        for (int b = 0; b < 4; b++) acc[a][b] = 0.f;

    const float4* Ax = (const float4*)d_xfrag + mt * 1024 + lane;
    const float4* Ah = (const float4*)d_hfrag[cur] + mt * 2048 + lane;
    const float4* Bi = (const float4*)d_wihf + jb * 512 + lane;    // gate stride 32768
    const float4* Bh = (const float4*)d_whhf + jb * 1024 + lane;   // gate stride 65536

    // gi = x @ w_ih^T  (K = 256 -> 16 kp), double-buffered
    {
        float4 a0 = __ldg(&Ax[0]), a1 = __ldg(&Ax[32]);
        float4 c0 = __ldg(&Bi[0]), c1 = __ldg(&Bi[32768]), c2 = __ldg(&Bi[65536]);
        #pragma unroll 1
        for (int kp = 0; kp < 16; kp += 2) {
            float4 a0n = __ldg(&Ax[(2*kp+2)*32]), a1n = __ldg(&Ax[(2*kp+3)*32]);
            float4 n0 = __ldg(&Bi[(kp+1)*32]);
            float4 n1 = __ldg(&Bi[32768 + (kp+1)*32]);
            float4 n2 = __ldg(&Bi[65536 + (kp+1)*32]);
            mma8(acc[0], a0, c0.x, c0.y); mma8(acc[0], a1, c0.z, c0.w);
            mma8(acc[1], a0, c1.x, c1.y); mma8(acc[1], a1, c1.z, c1.w);
            mma8(acc[2], a0, c2.x, c2.y); mma8(acc[2], a1, c2.z, c2.w);
            int kp2 = (kp + 2 < 16) ? kp + 2 : 15;
            a0 = __ldg(&Ax[(2*kp2)*32]); a1 = __ldg(&Ax[(2*kp2+1)*32]);
            c0 = __ldg(&Bi[kp2*32]);
            c1 = __ldg(&Bi[32768 + kp2*32]);
            c2 = __ldg(&Bi[65536 + kp2*32]);
            mma8(acc[0], a0n, n0.x, n0.y); mma8(acc[0], a1n, n0.z, n0.w);
            mma8(acc[1], a0n, n1.x, n1.y); mma8(acc[1], a1n, n1.z, n1.w);
            mma8(acc[2], a0n, n2.x, n2.y); mma8(acc[2], a1n, n2.z, n2.w);
        }
    }
    // gh = h @ w_hh^T  (K = 512 -> 32 kp), double-buffered
    {
        float4 a0 = __ldg(&Ah[0]), a1 = __ldg(&Ah[32]);
        float4 c0 = __ldg(&Bh[0]), c1 = __ldg(&Bh[65536]), c2 = __ldg(&Bh[131072]);
        #pragma unroll 1
        for (int kp = 0; kp < 32; kp += 2) {
            float4 a0n = __ldg(&Ah[(2*kp+2)*32]), a1n = __ldg(&Ah[(2*kp+3)*32]);
            float4 n0 = __ldg(&Bh[(kp+1)*32]);
            float4 n1 = __ldg(&Bh[65536 + (kp+1)*32]);
            float4 n2 = __ldg(&Bh[131072 + (kp+1)*32]);
            mma8(acc[3], a0, c0.x, c0.y); mma8(acc[3], a1, c0.z, c0.w);
            mma8(acc[4], a0, c1.x, c1.y); mma8(acc[4], a1, c1.z, c1.w);
            mma8(acc[5], a0, c2.x, c2.y); mma8(acc[5], a1, c2.z, c2.w);
            int kp2 = (kp + 2 < 32) ? kp + 2 : 31;
            a0 = __ldg(&Ah[(2*kp2)*32]); a1 = __ldg(&Ah[(2*kp2+1)*32]);
            c0 = __ldg(&Bh[kp2*32]);
            c1 = __ldg(&Bh[65536 + kp2*32]);
            c2 = __ldg(&Bh[131072 + kp2*32]);
            mma8(acc[3], a0n, n0.x, n0.y); mma8(acc[3], a1n, n0.z, n0.w);
            mma8(acc[4], a0n, n1.x, n1.y); mma8(acc[4], a1n, n1.z, n1.w);
            mma8(acc[5], a0n, n2.x, n2.y); mma8(acc[5], a1n, n2.z, n2.w);
        }
    }
    // gates + state update
    const float* hp = d_h[cur];
    float* hn = d_h[nxt];
    float* hf = d_hfrag[nxt];
    #pragma unroll
    for (int idx = 0; idx < 4; idx++) {
        int m = m0 + g + ((idx & 2) ? 8 : 0);
        int j = j0 + 2 * tig + (idx & 1);
        float ir  = acc[0][idx] + bih[j];            float hr  = acc[3][idx] + bhh[j];
        float iz  = acc[1][idx] + bih[DIMH + j];     float hz  = acc[4][idx] + bhh[DIMH + j];
        float inn = acc[2][idx] + bih[2*DIMH + j];   float hnn = acc[5][idx] + bhh[2*DIMH + j];
        float r  = 1.f / (1.f + expf(-(ir + hr)));
        float zg = 1.f / (1.f + expf(-(iz + hz)));
        float nn = tanhf(inn + r * hnn);
        float hv = (1.f - zg) * nn + zg * hp[m * DIMH + j];
        hn[m * DIMH + j] = hv;
        outh[m * DIMH + j] = hv;
        hf[frag_idx(m, j, 64)] = to_tf32(hv);
    }
}

// ---------------- pred + softmax partials per 128-vocab block ----------------
// block = 512 threads = 16 warps: mt = warp&3 (M tile), nh = warp>>2 (32-col vocab slice)
__global__ __launch_bounds__(512, 1) void pred_kernel(int parity,
        const float* __restrict__ gum, const float* __restrict__ outb,
        float* __restrict__ predout) {
    __shared__ __align__(16) float sEf[4 * 16 * 32 * 4];   // e in A-fragment layout, 32KB
    __shared__ float sS2[64][4];
    int tid = threadIdx.x, lane = tid & 31, warp = tid >> 5;
    int g = lane >> 2, tig = lane & 3;
    int mt = warp & 3, nh = warp >> 2;     // nh in 0..3
    int vb = blockIdx.x;

    // ---- phase 1: pred = h @ out_w^T  (M=64, N per warp = 32, K=512) ----
    float pacc[4][4];
    #pragma unroll
    for (int a = 0; a < 4; a++)
        #pragma unroll
        for (int b = 0; b < 4; b++) pacc[a][b] = 0.f;

    const float4* Af = (const float4*)d_hfrag[parity] + mt * 2048 + lane;
    // B base: [vb][nhOld = nh>>1][ntOld = (nh&1)*4 + nt'][kp][lane]
    const float4* Bf = (const float4*)d_outwf
        + (vb * 2 + (nh >> 1)) * 8192 + ((nh & 1) * 4) * 1024 + lane;

    {
        float4 a0 = __ldg(&Af[0]), a1 = __ldg(&Af[32]);
        float4 bc[4], bn[4];
        #pragma unroll
        for (int nt = 0; nt < 4; nt++) bc[nt] = __ldg(&Bf[nt * 1024]);
        #pragma unroll 1
        for (int kp = 0; kp < 32; kp += 2) {
            float4 a0n = __ldg(&Af[(2*kp+2)*32]), a1n = __ldg(&Af[(2*kp+3)*32]);
            #pragma unroll
            for (int nt = 0; nt < 4; nt++) bn[nt] = __ldg(&Bf[nt * 1024 + (kp+1)*32]);
            #pragma unroll
            for (int nt = 0; nt < 4; nt++) {
                mma8(pacc[nt], a0, bc[nt].x, bc[nt].y);
                mma8(pacc[nt], a1, bc[nt].z, bc[nt].w);
            }
            int kp2 = (kp + 2 < 32) ? kp + 2 : 31;
            a0 = __ldg(&Af[(2*kp2)*32]); a1 = __ldg(&Af[(2*kp2+1)*32]);
            #pragma unroll
            for (int nt = 0; nt < 4; nt++) bc[nt] = __ldg(&Bf[nt * 1024 + kp2*32]);
            #pragma unroll
            for (int nt = 0; nt < 4; nt++) {
                mma8(pacc[nt], a0n, bn[nt].x, bn[nt].y);
                mma8(pacc[nt], a1n, bn[nt].z, bn[nt].w);
            }
        }
    }

    // ---- epilogue: write pred, e = exp(pred + gumbel), stash e-frags + row sums ----
    int rA = mt * 16 + g, rB = rA + 8;
    float slo = 0.f, shi = 0.f;
    #pragma unroll
    for (int nt = 0; nt < 4; nt++) {
        int vcol = nh * 32 + nt * 8 + 2 * tig;
        int vg = vb * 128 + vcol;
        float ob0 = __ldg(&outb[vg]), ob1 = __ldg(&outb[vg + 1]);
        float p00 = pacc[nt][0] + ob0, p01 = pacc[nt][1] + ob1;
        float p10 = pacc[nt][2] + ob0, p11 = pacc[nt][3] + ob1;
        *(float2*)&predout[rA * VOCAB + vg] = make_float2(p00, p01);
        *(float2*)&predout[rB * VOCAB + vg] = make_float2(p10, p11);
        float2 gA = *(const float2*)&gum[rA * VOCAB + vg];
        float2 gB = *(const float2*)&gum[rB * VOCAB + vg];
        float e00 = __expf(p00 + gA.x), e01 = __expf(p01 + gA.y);
        float e10 = __expf(p10 + gB.x), e11 = __expf(p11 + gB.y);
        slo += e00 + e01; shi += e10 + e11;
        // scatter into A-fragment layout (k8 dim = 16 for K=128)
        int k8 = nh * 4 + nt;
        int kc0 = 2 * tig, kc1 = 2 * tig + 1;
        int lane0 = (g << 2) | (kc0 & 3), slot0h = (kc0 >= 4) ? 2 : 0;
        int lane1 = (g << 2) | (kc1 & 3), slot1h = (kc1 >= 4) ? 2 : 0;
        float* baseA0 = &sEf[((mt * 16 + k8) * 32 + lane0) * 4];
        float* baseA1 = &sEf[((mt * 16 + k8) * 32 + lane1) * 4];
        baseA0[slot0h + 0] = to_tf32(e00);
        baseA1[slot1h + 0] = to_tf32(e01);
        baseA0[slot0h + 1] = to_tf32(e10);
        baseA1[slot1h + 1] = to_tf32(e11);
    }
    slo += __shfl_down_sync(0xffffffffu, slo, 1);
    slo += __shfl_down_sync(0xffffffffu, slo, 2);
    shi += __shfl_down_sync(0xffffffffu, shi, 1);
    shi += __shfl_down_sync(0xffffffffu, shi, 2);
    if (tig == 0) {                     // unique (row, nh) writer: deterministic
        sS2[rA][nh] = slo;
        sS2[rB][nh] = shi;
    }
    __syncthreads();
    if (tid < 64) d_pS[vb * 64 + tid] = (sS2[tid][0] + sS2[tid][1])
                                      + (sS2[tid][2] + sS2[tid][3]);

    // ---- phase 3: partial E = e @ emb_chunk  (M=64, N per warp = 64, K=128) ----
    const float4* sE4 = (const float4*)sEf + mt * 512 + lane;
    const float4* Ef = (const float4*)d_embf
        + (vb * 2 + (nh >> 1)) * 4096 + ((nh & 1) * 8) * 256 + lane;
    float* pEblk = d_pE + vb * (BATCH * EMBED);

    float eacc[8][4];
    #pragma unroll
    for (int a = 0; a < 8; a++)
        #pragma unroll
        for (int b = 0; b < 4; b++) eacc[a][b] = 0.f;

    #pragma unroll 2
    for (int kp = 0; kp < 8; kp++) {
        float4 a0 = sE4[(2 * kp) * 32];
        float4 a1 = sE4[(2 * kp + 1) * 32];
        #pragma unroll
        for (int t = 0; t < 8; t++) {
            float4 b = __ldg(&Ef[(t * 8 + kp) * 32]);
            mma8(eacc[t], a0, b.x, b.y);
            mma8(eacc[t], a1, b.z, b.w);
        }
    }
    #pragma unroll
    for (int t = 0; t < 8; t++) {
        int c = nh * 64 + t * 8 + 2 * tig;
        *(float2*)&pEblk[rA * EMBED + c] = make_float2(eacc[t][0], eacc[t][1]);
        *(float2*)&pEblk[rB * EMBED + c] = make_float2(eacc[t][2], eacc[t][3]);
    }
}

// ---------------- reduce partials -> x_next (fragment layout) ----------------
// grid (64, 4), block 64: blockIdx.x = batch row, blockIdx.y picks 64 channels
__global__ __launch_bounds__(64) void reduce_kernel() {
    __shared__ float sred[64];
    int b = blockIdx.x, tid = threadIdx.x;
    float s = 0.f;
    for (int k = tid; k < NPB; k += 64) s += d_pS[k * 64 + b];
    sred[tid] = s;
    __syncthreads();
    #pragma unroll
    for (int off = 32; off > 0; off >>= 1) {
        if (tid < off) sred[tid] += sred[tid + off];
        __syncthreads();
    }
    float sinv = 1.f / (GAMMA * sred[0]);
    int c = blockIdx.y * 64 + tid;
    float acc = 0.f;
    const float* p = d_pE + b * EMBED + c;
    #pragma unroll 25
    for (int k = 0; k < NPB; k++) acc += p[k * (BATCH * EMBED)];
    d_xfrag[frag_idx(b, c, 32)] = to_tf32(acc * sinv);
}

// ---------------- launch ----------------
extern "C" void kernel_launch(void* const* d_in, const int* in_sizes, int n_in,
                              void* d_out, int out_size) {
    const float* z      = (const float*)d_in[0];
    const float* labels = (const float*)d_in[1];
    // d_in[2] src, d_in[3] src_len: unused by the transfered=True path
    const float* gum    = (const float*)d_in[4];
    const float* emb    = (const float*)d_in[5];
    const float* fcw    = (const float*)d_in[6];
    const float* fcb    = (const float*)d_in[7];
    const float* wih    = (const float*)d_in[8];
    const float* whh    = (const float*)d_in[9];
    const float* bih    = (const float*)d_in[10];
    const float* bhh    = (const float*)d_in[11];
    const float* outw   = (const float*)d_in[12];
    const float* outb   = (const float*)d_in[13];
    float* out = (float*)d_out;

    prep_kernel<<<2048, 256>>>(outw, emb, wih, whh);
    init_kernel<<<1024, 256>>>(z, labels, emb, fcw, fcb, out);

    for (int i = 0; i < TSTEPS; i++) {
        int cur = i & 1, nxt = cur ^ 1;
        gru_kernel<<<64, 128>>>(cur, bih, bhh, out + (int64_t)(2 + i) * OUT_H_STRIDE);
        pred_kernel<<<NPB, 512>>>(nxt, gum + (int64_t)i * OUT_P_STRIDE,
                                  outb, out + PRED_OFF + (int64_t)(i + 1) * OUT_P_STRIDE);
        if (i < TSTEPS - 1) reduce_kernel<<<dim3(64, 4), 64>>>();
    }
}

// round 6
// speedup vs baseline: 2.0606x; 1.0154x over previous
#include <cuda_runtime.h>
#include <cstdint>

#define BATCH 64
#define VOCAB 16000
#define EMBED 256
#define DIMH  512
#define G3    1536
#define TSTEPS 63
#define GAMMA 0.1f
#define VC    128
#define NPB   125   // pred blocks = VOCAB / VC

#define OUT_H_STRIDE (BATCH*DIMH)     // 32768
#define OUT_P_STRIDE (BATCH*VOCAB)    // 1024000
#define PRED_OFF (65*OUT_H_STRIDE)    // 2129920

// ---------------- scratch (device globals; no allocation) ----------------
__device__ __align__(16) float d_h[2][BATCH*DIMH];      // fp32 hidden state (row-major, ping-pong)
__device__ __align__(16) float d_hfrag[2][BATCH*DIMH];  // tf32 hidden state, A-fragment layout
__device__ __align__(16) float d_xfrag[BATCH*EMBED];    // tf32 soft embedding, A-fragment layout
__device__ __align__(16) float d_pE[NPB*BATCH*EMBED];   // partial E sums per vocab block
__device__ float d_pS[NPB*BATCH];                       // partial softmax denominators
// B-operand fragment layouts (precomputed once, tf32-rounded)
__device__ __align__(16) float d_outwf[VOCAB*DIMH];   // [vb125][nh2][nt8][kp32][lane32][4]
__device__ __align__(16) float d_embf[VOCAB*EMBED];   // [vb125][nh2][nt16][kp8][lane32][4]
__device__ __align__(16) float d_wihf[G3*EMBED];      // [gate3][jb64][kp16][lane32][4]
__device__ __align__(16) float d_whhf[G3*DIMH];       // [gate3][jb64][kp32][lane32][4]

// ---------------- helpers ----------------
__device__ __forceinline__ float to_tf32(float x) {
    unsigned u;
    asm("cvt.rna.tf32.f32 %0, %1;" : "=r"(u) : "f"(x));
    return __uint_as_float(u);
}

__device__ __forceinline__ uint64_t mk_evict_last_policy() {
    uint64_t pol;
    asm("createpolicy.fractional.L2::evict_last.b64 %0, 1.0;" : "=l"(pol));
    return pol;
}

// weight load: non-coherent, L2 evict_last (keep weights resident across steps)
__device__ __forceinline__ float4 ldgEL(const float4* p, uint64_t pol) {
    float4 v;
    asm volatile("ld.global.nc.L2::cache_hint.v4.f32 {%0,%1,%2,%3}, [%4], %5;"
        : "=f"(v.x), "=f"(v.y), "=f"(v.z), "=f"(v.w) : "l"(p), "l"(pol));
    return v;
}

__device__ __forceinline__ void mma8(float* c, float4 a, float b0, float b1) {
    asm volatile(
        "mma.sync.aligned.m16n8k8.row.col.f32.tf32.tf32.f32 "
        "{%0,%1,%2,%3}, {%4,%5,%6,%7}, {%8,%9}, {%0,%1,%2,%3};\n"
        : "+f"(c[0]), "+f"(c[1]), "+f"(c[2]), "+f"(c[3])
        : "r"(__float_as_uint(a.x)), "r"(__float_as_uint(a.y)),
          "r"(__float_as_uint(a.z)), "r"(__float_as_uint(a.w)),
          "r"(__float_as_uint(b0)), "r"(__float_as_uint(b1)));
}

// A-fragment scatter position for value at (row m in 0..63, col k)
__device__ __forceinline__ int frag_idx(int m, int k, int k8dim) {
    int mr = m & 15, kc = k & 7, k8 = k >> 3, mt = m >> 4;
    int lane = ((mr & 7) << 2) | (kc & 3);
    int slot = ((kc >= 4) ? 2 : 0) | ((mr >= 8) ? 1 : 0);
    return ((mt * k8dim + k8) * 32 + lane) * 4 + slot;
}

// ---------------- prep: build tf32 fragment-layout weights ----------------
__global__ void prep_kernel(const float* __restrict__ outw, const float* __restrict__ emb,
                            const float* __restrict__ wih,  const float* __restrict__ whh) {
    const int T1 = VOCAB*DIMH/4;            // 2048000
    const int T2 = T1 + VOCAB*EMBED/4;      // +1024000
    const int T3 = T2 + G3*EMBED/4;         // +98304
    const int T4 = T3 + G3*DIMH/4;          // +196608
    for (int gid = blockIdx.x * blockDim.x + threadIdx.x; gid < T4;
         gid += gridDim.x * blockDim.x) {
        if (gid < T1) {
            int lane = gid & 31, kp = (gid >> 5) & 31, nt = (gid >> 10) & 7;
            int nh = (gid >> 13) & 1, vb = gid >> 14;
            int g = lane >> 2, tig = lane & 3;
            int n = vb * 128 + nh * 64 + nt * 8 + g;
            const float* r = outw + n * DIMH + kp * 16 + tig;
            float4 q = make_float4(to_tf32(r[0]), to_tf32(r[4]), to_tf32(r[8]), to_tf32(r[12]));
            ((float4*)d_outwf)[gid] = q;
        } else if (gid < T2) {
            int id = gid - T1;
            int lane = id & 31, kp = (id >> 5) & 7, nt = (id >> 8) & 15;
            int nh = (id >> 12) & 1, vb = id >> 13;
            int g = lane >> 2, tig = lane & 3;
            int n = nh * 128 + nt * 8 + g;
            int k0 = vb * 128 + kp * 16 + tig;
            float4 q = make_float4(to_tf32(emb[(int64_t)k0 * EMBED + n]),
                                   to_tf32(emb[(int64_t)(k0 + 4) * EMBED + n]),
                                   to_tf32(emb[(int64_t)(k0 + 8) * EMBED + n]),
                                   to_tf32(emb[(int64_t)(k0 + 12) * EMBED + n]));
            ((float4*)d_embf)[id] = q;
        } else if (gid < T3) {
            int id = gid - T2;
            int lane = id & 31, kp = (id >> 5) & 15, jb = (id >> 9) & 63, gate = id >> 15;
            int g = lane >> 2, tig = lane & 3;
            int row = gate * DIMH + jb * 8 + g;
            const float* r = wih + row * EMBED + kp * 16 + tig;
            float4 q = make_float4(to_tf32(r[0]), to_tf32(r[4]), to_tf32(r[8]), to_tf32(r[12]));
            ((float4*)d_wihf)[id] = q;
        } else {
            int id = gid - T3;
            int lane = id & 31, kp = (id >> 5) & 31, jb = (id >> 10) & 63, gate = id >> 16;
            int g = lane >> 2, tig = lane & 3;
            int row = gate * DIMH + jb * 8 + g;
            const float* r = whh + row * DIMH + kp * 16 + tig;
            float4 q = make_float4(to_tf32(r[0]), to_tf32(r[4]), to_tf32(r[8]), to_tf32(r[12]));
            ((float4*)d_whhf)[id] = q;
        }
    }
}

// ---------------- init: h0, x0, zero rows ----------------
__global__ void init_kernel(const float* __restrict__ z, const float* __restrict__ labels,
                            const float* __restrict__ emb, const float* __restrict__ fcw,
                            const float* __restrict__ fcb, float* __restrict__ out) {
    int64_t i = (int64_t)blockIdx.x * blockDim.x + threadIdx.x;
    int64_t stride = (int64_t)gridDim.x * blockDim.x;
    const int64_t NH0 = 32768;              // h0 -> outputs[0] + state
    const int64_t NZ  = 65536;              // outputs[1] = 0
    const int64_t NX  = 81920;              // x0 = emb[<sos>]
    const int64_t NP  = NX + (int64_t)OUT_P_STRIDE; // predictions[0] = 0
    for (; i < NP; i += stride) {
        if (i < NH0) {
            int b = (int)(i >> 9), j = (int)(i & 511);
            float v = (j < 64) ? (1.f - labels[b]) * fcw[j] + fcb[j]
                               : z[b * 448 + (j - 64)];
            d_h[0][i] = v; out[i] = v;
            d_hfrag[0][frag_idx(b, j, 64)] = to_tf32(v);
        } else if (i < NZ) {
            out[i] = 0.f;
        } else if (i < NX) {
            int l = (int)(i - NZ); int b = l >> 8, c = l & 255;
            d_xfrag[frag_idx(b, c, 32)] = to_tf32(emb[2 * EMBED + c]);   // IDX_SOS = 2
        } else {
            out[PRED_OFF + (i - NX)] = 0.f;
        }
    }
}

// ---------------- GRU cell: h_new = GRU(x, h) ----------------
__global__ __launch_bounds__(128) void gru_kernel(int cur,
        const float* __restrict__ bih, const float* __restrict__ bhh,
        float* __restrict__ outh) {
    const int nxt = cur ^ 1;
    int tid = threadIdx.x, lane = tid & 31, mt = tid >> 5;
    int g = lane >> 2, tig = lane & 3;
    int jb = blockIdx.x;
    int j0 = jb * 8;
    int m0 = mt * 16;
    uint64_t pol = mk_evict_last_policy();

    float acc[6][4];
    #pragma unroll
    for (int a = 0; a < 6; a++)
        #pragma unroll
        for (int b = 0; b < 4; b++) acc[a][b] = 0.f;

    const float4* Ax = (const float4*)d_xfrag + mt * 1024 + lane;
    const float4* Ah = (const float4*)d_hfrag[cur] + mt * 2048 + lane;
    const float4* Bi = (const float4*)d_wihf + jb * 512 + lane;    // gate stride 32768
    const float4* Bh = (const float4*)d_whhf + jb * 1024 + lane;   // gate stride 65536

    // gi = x @ w_ih^T  (K = 256 -> 16 kp), double-buffered
    {
        float4 a0 = __ldg(&Ax[0]), a1 = __ldg(&Ax[32]);
        float4 c0 = ldgEL(&Bi[0], pol), c1 = ldgEL(&Bi[32768], pol), c2 = ldgEL(&Bi[65536], pol);
        #pragma unroll 1
        for (int kp = 0; kp < 16; kp += 2) {
            float4 a0n = __ldg(&Ax[(2*kp+2)*32]), a1n = __ldg(&Ax[(2*kp+3)*32]);
            float4 n0 = ldgEL(&Bi[(kp+1)*32], pol);
            float4 n1 = ldgEL(&Bi[32768 + (kp+1)*32], pol);
            float4 n2 = ldgEL(&Bi[65536 + (kp+1)*32], pol);
            mma8(acc[0], a0, c0.x, c0.y); mma8(acc[0], a1, c0.z, c0.w);
            mma8(acc[1], a0, c1.x, c1.y); mma8(acc[1], a1, c1.z, c1.w);
            mma8(acc[2], a0, c2.x, c2.y); mma8(acc[2], a1, c2.z, c2.w);
            int kp2 = (kp + 2 < 16) ? kp + 2 : 15;
            a0 = __ldg(&Ax[(2*kp2)*32]); a1 = __ldg(&Ax[(2*kp2+1)*32]);
            c0 = ldgEL(&Bi[kp2*32], pol);
            c1 = ldgEL(&Bi[32768 + kp2*32], pol);
            c2 = ldgEL(&Bi[65536 + kp2*32], pol);
            mma8(acc[0], a0n, n0.x, n0.y); mma8(acc[0], a1n, n0.z, n0.w);
            mma8(acc[1], a0n, n1.x, n1.y); mma8(acc[1], a1n, n1.z, n1.w);
            mma8(acc[2], a0n, n2.x, n2.y); mma8(acc[2], a1n, n2.z, n2.w);
        }
    }
    // gh = h @ w_hh^T  (K = 512 -> 32 kp), double-buffered
    {
        float4 a0 = __ldg(&Ah[0]), a1 = __ldg(&Ah[32]);
        float4 c0 = ldgEL(&Bh[0], pol), c1 = ldgEL(&Bh[65536], pol), c2 = ldgEL(&Bh[131072], pol);
        #pragma unroll 1
        for (int kp = 0; kp < 32; kp += 2) {
            float4 a0n = __ldg(&Ah[(2*kp+2)*32]), a1n = __ldg(&Ah[(2*kp+3)*32]);
            float4 n0 = ldgEL(&Bh[(kp+1)*32], pol);
            float4 n1 = ldgEL(&Bh[65536 + (kp+1)*32], pol);
            float4 n2 = ldgEL(&Bh[131072 + (kp+1)*32], pol);
            mma8(acc[3], a0, c0.x, c0.y); mma8(acc[3], a1, c0.z, c0.w);
            mma8(acc[4], a0, c1.x, c1.y); mma8(acc[4], a1, c1.z, c1.w);
            mma8(acc[5], a0, c2.x, c2.y); mma8(acc[5], a1, c2.z, c2.w);
            int kp2 = (kp + 2 < 32) ? kp + 2 : 31;
            a0 = __ldg(&Ah[(2*kp2)*32]); a1 = __ldg(&Ah[(2*kp2+1)*32]);
            c0 = ldgEL(&Bh[kp2*32], pol);
            c1 = ldgEL(&Bh[65536 + kp2*32], pol);
            c2 = ldgEL(&Bh[131072 + kp2*32], pol);
            mma8(acc[3], a0n, n0.x, n0.y); mma8(acc[3], a1n, n0.z, n0.w);
            mma8(acc[4], a0n, n1.x, n1.y); mma8(acc[4], a1n, n1.z, n1.w);
            mma8(acc[5], a0n, n2.x, n2.y); mma8(acc[5], a1n, n2.z, n2.w);
        }
    }
    // gates + state update
    const float* hp = d_h[cur];
    float* hn = d_h[nxt];
    float* hf = d_hfrag[nxt];
    #pragma unroll
    for (int idx = 0; idx < 4; idx++) {
        int m = m0 + g + ((idx & 2) ? 8 : 0);
        int j = j0 + 2 * tig + (idx & 1);
        float ir  = acc[0][idx] + bih[j];            float hr  = acc[3][idx] + bhh[j];
        float iz  = acc[1][idx] + bih[DIMH + j];     float hz  = acc[4][idx] + bhh[DIMH + j];
        float inn = acc[2][idx] + bih[2*DIMH + j];   float hnn = acc[5][idx] + bhh[2*DIMH + j];
        float r  = 1.f / (1.f + expf(-(ir + hr)));
        float zg = 1.f / (1.f + expf(-(iz + hz)));
        float nn = tanhf(inn + r * hnn);
        float hv = (1.f - zg) * nn + zg * hp[m * DIMH + j];
        hn[m * DIMH + j] = hv;
        __stcs(&outh[m * DIMH + j], hv);
        hf[frag_idx(m, j, 64)] = to_tf32(hv);
    }
}

// ---------------- pred + softmax partials per 128-vocab block ----------------
// block = 512 threads = 16 warps: mt = warp&3 (M tile), nh = warp>>2 (32-col vocab slice)
__global__ __launch_bounds__(512, 1) void pred_kernel(int parity,
        const float* __restrict__ gum, const float* __restrict__ outb,
        float* __restrict__ predout) {
    __shared__ __align__(16) float sEf[4 * 16 * 32 * 4];   // e in A-fragment layout, 32KB
    __shared__ float sS2[64][4];
    int tid = threadIdx.x, lane = tid & 31, warp = tid >> 5;
    int g = lane >> 2, tig = lane & 3;
    int mt = warp & 3, nh = warp >> 2;     // nh in 0..3
    int vb = blockIdx.x;
    uint64_t pol = mk_evict_last_policy();

    // ---- phase 1: pred = h @ out_w^T  (M=64, N per warp = 32, K=512) ----
    float pacc[4][4];
    #pragma unroll
    for (int a = 0; a < 4; a++)
        #pragma unroll
        for (int b = 0; b < 4; b++) pacc[a][b] = 0.f;

    const float4* Af = (const float4*)d_hfrag[parity] + mt * 2048 + lane;
    const float4* Bf = (const float4*)d_outwf
        + (vb * 2 + (nh >> 1)) * 8192 + ((nh & 1) * 4) * 1024 + lane;

    {
        float4 a0 = __ldg(&Af[0]), a1 = __ldg(&Af[32]);
        float4 bc[4], bn[4];
        #pragma unroll
        for (int nt = 0; nt < 4; nt++) bc[nt] = ldgEL(&Bf[nt * 1024], pol);
        #pragma unroll 1
        for (int kp = 0; kp < 32; kp += 2) {
            float4 a0n = __ldg(&Af[(2*kp+2)*32]), a1n = __ldg(&Af[(2*kp+3)*32]);
            #pragma unroll
            for (int nt = 0; nt < 4; nt++) bn[nt] = ldgEL(&Bf[nt * 1024 + (kp+1)*32], pol);
            #pragma unroll
            for (int nt = 0; nt < 4; nt++) {
                mma8(pacc[nt], a0, bc[nt].x, bc[nt].y);
                mma8(pacc[nt], a1, bc[nt].z, bc[nt].w);
            }
            int kp2 = (kp + 2 < 32) ? kp + 2 : 31;
            a0 = __ldg(&Af[(2*kp2)*32]); a1 = __ldg(&Af[(2*kp2+1)*32]);
            #pragma unroll
            for (int nt = 0; nt < 4; nt++) bc[nt] = ldgEL(&Bf[nt * 1024 + kp2*32], pol);
            #pragma unroll
            for (int nt = 0; nt < 4; nt++) {
                mma8(pacc[nt], a0n, bn[nt].x, bn[nt].y);
                mma8(pacc[nt], a1n, bn[nt].z, bn[nt].w);
            }
        }
    }

    // ---- epilogue: write pred (streaming), e = exp(pred + gumbel), stash e-frags ----
    int rA = mt * 16 + g, rB = rA + 8;
    float slo = 0.f, shi = 0.f;
    #pragma unroll
    for (int nt = 0; nt < 4; nt++) {
        int vcol = nh * 32 + nt * 8 + 2 * tig;
        int vg = vb * 128 + vcol;
        float ob0 = __ldg(&outb[vg]), ob1 = __ldg(&outb[vg + 1]);
        float p00 = pacc[nt][0] + ob0, p01 = pacc[nt][1] + ob1;
        float p10 = pacc[nt][2] + ob0, p11 = pacc[nt][3] + ob1;
        __stcs((float2*)&predout[rA * VOCAB + vg], make_float2(p00, p01));
        __stcs((float2*)&predout[rB * VOCAB + vg], make_float2(p10, p11));
        float2 gA = __ldcs((const float2*)&gum[rA * VOCAB + vg]);
        float2 gB = __ldcs((const float2*)&gum[rB * VOCAB + vg]);
        float e00 = __expf(p00 + gA.x), e01 = __expf(p01 + gA.y);
        float e10 = __expf(p10 + gB.x), e11 = __expf(p11 + gB.y);
        slo += e00 + e01; shi += e10 + e11;
        // scatter into A-fragment layout (k8 dim = 16 for K=128)
        int k8 = nh * 4 + nt;
        int kc0 = 2 * tig, kc1 = 2 * tig + 1;
        int lane0 = (g << 2) | (kc0 & 3), slot0h = (kc0 >= 4) ? 2 : 0;
        int lane1 = (g << 2) | (kc1 & 3), slot1h = (kc1 >= 4) ? 2 : 0;
        float* baseA0 = &sEf[((mt * 16 + k8) * 32 + lane0) * 4];
        float* baseA1 = &sEf[((mt * 16 + k8) * 32 + lane1) * 4];
        baseA0[slot0h + 0] = to_tf32(e00);
        baseA1[slot1h + 0] = to_tf32(e01);
        baseA0[slot0h + 1] = to_tf32(e10);
        baseA1[slot1h + 1] = to_tf32(e11);
    }
    slo += __shfl_down_sync(0xffffffffu, slo, 1);
    slo += __shfl_down_sync(0xffffffffu, slo, 2);
    shi += __shfl_down_sync(0xffffffffu, shi, 1);
    shi += __shfl_down_sync(0xffffffffu, shi, 2);
    if (tig == 0) {                     // unique (row, nh) writer: deterministic
        sS2[rA][nh] = slo;
        sS2[rB][nh] = shi;
    }
    __syncthreads();
    if (tid < 64) d_pS[vb * 64 + tid] = (sS2[tid][0] + sS2[tid][1])
                                      + (sS2[tid][2] + sS2[tid][3]);

    // ---- phase 3: partial E = e @ emb_chunk  (M=64, N per warp = 64, K=128) ----
    const float4* sE4 = (const float4*)sEf + mt * 512 + lane;
    const float4* Ef = (const float4*)d_embf
        + (vb * 2 + (nh >> 1)) * 4096 + ((nh & 1) * 8) * 256 + lane;
    float* pEblk = d_pE + vb * (BATCH * EMBED);

    float eacc[8][4];
    #pragma unroll
    for (int a = 0; a < 8; a++)
        #pragma unroll
        for (int b = 0; b < 4; b++) eacc[a][b] = 0.f;

    #pragma unroll 2
    for (int kp = 0; kp < 8; kp++) {
        float4 a0 = sE4[(2 * kp) * 32];
        float4 a1 = sE4[(2 * kp + 1) * 32];
        #pragma unroll
        for (int t = 0; t < 8; t++) {
            float4 b = ldgEL(&Ef[(t * 8 + kp) * 32], pol);
            mma8(eacc[t], a0, b.x, b.y);
            mma8(eacc[t], a1, b.z, b.w);
        }
    }
    #pragma unroll
    for (int t = 0; t < 8; t++) {
        int c = nh * 64 + t * 8 + 2 * tig;
        __stcs((float2*)&pEblk[rA * EMBED + c], make_float2(eacc[t][0], eacc[t][1]));
        __stcs((float2*)&pEblk[rB * EMBED + c], make_float2(eacc[t][2], eacc[t][3]));
    }
}

// ---------------- reduce partials -> x_next (fragment layout) ----------------
// grid (64, 4), block 64: blockIdx.x = batch row, blockIdx.y picks 64 channels
__global__ __launch_bounds__(64) void reduce_kernel() {
    __shared__ float sred[64];
    int b = blockIdx.x, tid = threadIdx.x;
    float s = 0.f;
    for (int k = tid; k < NPB; k += 64) s += d_pS[k * 64 + b];
    sred[tid] = s;
    __syncthreads();
    #pragma unroll
    for (int off = 32; off > 0; off >>= 1) {
        if (tid < off) sred[tid] += sred[tid + off];
        __syncthreads();
    }
    float sinv = 1.f / (GAMMA * sred[0]);
    int c = blockIdx.y * 64 + tid;
    float acc = 0.f;
    const float* p = d_pE + b * EMBED + c;
    #pragma unroll 25
    for (int k = 0; k < NPB; k++) acc += __ldcs(&p[k * (BATCH * EMBED)]);
    d_xfrag[frag_idx(b, c, 32)] = to_tf32(acc * sinv);
}

// ---------------- launch ----------------
extern "C" void kernel_launch(void* const* d_in, const int* in_sizes, int n_in,
                              void* d_out, int out_size) {
    const float* z      = (const float*)d_in[0];
    const float* labels = (const float*)d_in[1];
    // d_in[2] src, d_in[3] src_len: unused by the transfered=True path
    const float* gum    = (const float*)d_in[4];
    const float* emb    = (const float*)d_in[5];
    const float* fcw    = (const float*)d_in[6];
    const float* fcb    = (const float*)d_in[7];
    const float* wih    = (const float*)d_in[8];
    const float* whh    = (const float*)d_in[9];
    const float* bih    = (const float*)d_in[10];
    const float* bhh    = (const float*)d_in[11];
    const float* outw   = (const float*)d_in[12];
    const float* outb   = (const float*)d_in[13];
    float* out = (float*)d_out;

    prep_kernel<<<2048, 256>>>(outw, emb, wih, whh);
    init_kernel<<<1024, 256>>>(z, labels, emb, fcw, fcb, out);

    for (int i = 0; i < TSTEPS; i++) {
        int cur = i & 1, nxt = cur ^ 1;
        gru_kernel<<<64, 128>>>(cur, bih, bhh, out + (int64_t)(2 + i) * OUT_H_STRIDE);
        pred_kernel<<<NPB, 512>>>(nxt, gum + (int64_t)i * OUT_P_STRIDE,
                                  outb, out + PRED_OFF + (int64_t)(i + 1) * OUT_P_STRIDE);
        if (i < TSTEPS - 1) reduce_kernel<<<dim3(64, 4), 64>>>();
    }
}

// round 8
// speedup vs baseline: 2.4172x; 1.1730x over previous
#include <cuda_runtime.h>
#include <cstdint>

#define BATCH 64
#define VOCAB 16000
#define EMBED 256
#define DIMH  512
#define G3    1536
#define TSTEPS 63
#define GAMMA 0.1f
#define VC    128
#define NPB   125   // pred blocks = VOCAB / VC

#define OUT_H_STRIDE (BATCH*DIMH)     // 32768
#define OUT_P_STRIDE (BATCH*VOCAB)    // 1024000
#define PRED_OFF (65*OUT_H_STRIDE)    // 2129920

// ---------------- scratch (device globals; no allocation) ----------------
__device__ __align__(16) float d_h[2][BATCH*DIMH];      // fp32 hidden state (row-major, ping-pong)
__device__ __align__(16) float d_hfrag[2][BATCH*DIMH];  // tf32 hidden state, A-fragment layout
__device__ __align__(16) float d_xfrag[BATCH*EMBED];    // tf32 soft embedding, A-fragment layout
__device__ __align__(16) float d_pE[NPB*BATCH*EMBED];   // partial E sums per vocab block
__device__ float d_pS[NPB*BATCH];                       // partial softmax denominators
// B-operand fragment layouts (precomputed once, tf32-rounded)
__device__ __align__(16) float d_outwf[VOCAB*DIMH];   // [vb125][nh2][nt8][kp32][lane32][4]
__device__ __align__(16) float d_embf[VOCAB*EMBED];   // [vb125][nh2][nt16][kp8][lane32][4]
__device__ __align__(16) float d_wihf[G3*EMBED];      // [gate3][jb64][kp16][lane32][4]
__device__ __align__(16) float d_whhf[G3*DIMH];       // [gate3][jb64][kp32][lane32][4]

// ---------------- helpers ----------------
__device__ __forceinline__ float to_tf32(float x) {
    unsigned u;
    asm("cvt.rna.tf32.f32 %0, %1;" : "=r"(u) : "f"(x));
    return __uint_as_float(u);
}

__device__ __forceinline__ uint64_t mk_evict_last_policy() {
    uint64_t pol;
    asm("createpolicy.fractional.L2::evict_last.b64 %0, 1.0;" : "=l"(pol));
    return pol;
}

__device__ __forceinline__ float4 ldgEL(const float4* p, uint64_t pol) {
    float4 v;
    asm volatile("ld.global.nc.L2::cache_hint.v4.f32 {%0,%1,%2,%3}, [%4], %5;"
        : "=f"(v.x), "=f"(v.y), "=f"(v.z), "=f"(v.w) : "l"(p), "l"(pol));
    return v;
}

__device__ __forceinline__ void mma8(float* c, float4 a, float b0, float b1) {
    asm volatile(
        "mma.sync.aligned.m16n8k8.row.col.f32.tf32.tf32.f32 "
        "{%0,%1,%2,%3}, {%4,%5,%6,%7}, {%8,%9}, {%0,%1,%2,%3};\n"
        : "+f"(c[0]), "+f"(c[1]), "+f"(c[2]), "+f"(c[3])
        : "r"(__float_as_uint(a.x)), "r"(__float_as_uint(a.y)),
          "r"(__float_as_uint(a.z)), "r"(__float_as_uint(a.w)),
          "r"(__float_as_uint(b0)), "r"(__float_as_uint(b1)));
}

// A-fragment scatter position for value at (row m in 0..63, col k)
__device__ __forceinline__ int frag_idx(int m, int k, int k8dim) {
    int mr = m & 15, kc = k & 7, k8 = k >> 3, mt = m >> 4;
    int lane = ((mr & 7) << 2) | (kc & 3);
    int slot = ((kc >= 4) ? 2 : 0) | ((mr >= 8) ? 1 : 0);
    return ((mt * k8dim + k8) * 32 + lane) * 4 + slot;
}

// ---------------- prep: build tf32 fragment-layout weights ----------------
__global__ void prep_kernel(const float* __restrict__ outw, const float* __restrict__ emb,
                            const float* __restrict__ wih,  const float* __restrict__ whh) {
    const int T1 = VOCAB*DIMH/4;            // 2048000
    const int T2 = T1 + VOCAB*EMBED/4;      // +1024000
    const int T3 = T2 + G3*EMBED/4;         // +98304
    const int T4 = T3 + G3*DIMH/4;          // +196608
    for (int gid = blockIdx.x * blockDim.x + threadIdx.x; gid < T4;
         gid += gridDim.x * blockDim.x) {
        if (gid < T1) {
            int lane = gid & 31, kp = (gid >> 5) & 31, nt = (gid >> 10) & 7;
            int nh = (gid >> 13) & 1, vb = gid >> 14;
            int g = lane >> 2, tig = lane & 3;
            int n = vb * 128 + nh * 64 + nt * 8 + g;
            const float* r = outw + n * DIMH + kp * 16 + tig;
            float4 q = make_float4(to_tf32(r[0]), to_tf32(r[4]), to_tf32(r[8]), to_tf32(r[12]));
            ((float4*)d_outwf)[gid] = q;
        } else if (gid < T2) {
            int id = gid - T1;
            int lane = id & 31, kp = (id >> 5) & 7, nt = (id >> 8) & 15;
            int nh = (id >> 12) & 1, vb = id >> 13;
            int g = lane >> 2, tig = lane & 3;
            int n = nh * 128 + nt * 8 + g;
            int k0 = vb * 128 + kp * 16 + tig;
            float4 q = make_float4(to_tf32(emb[(int64_t)k0 * EMBED + n]),
                                   to_tf32(emb[(int64_t)(k0 + 4) * EMBED + n]),
                                   to_tf32(emb[(int64_t)(k0 + 8) * EMBED + n]),
                                   to_tf32(emb[(int64_t)(k0 + 12) * EMBED + n]));
            ((float4*)d_embf)[id] = q;
        } else if (gid < T3) {
            int id = gid - T2;
            int lane = id & 31, kp = (id >> 5) & 15, jb = (id >> 9) & 63, gate = id >> 15;
            int g = lane >> 2, tig = lane & 3;
            int row = gate * DIMH + jb * 8 + g;
            const float* r = wih + row * EMBED + kp * 16 + tig;
            float4 q = make_float4(to_tf32(r[0]), to_tf32(r[4]), to_tf32(r[8]), to_tf32(r[12]));
            ((float4*)d_wihf)[id] = q;
        } else {
            int id = gid - T3;
            int lane = id & 31, kp = (id >> 5) & 31, jb = (id >> 10) & 63, gate = id >> 16;
            int g = lane >> 2, tig = lane & 3;
            int row = gate * DIMH + jb * 8 + g;
            const float* r = whh + row * DIMH + kp * 16 + tig;
            float4 q = make_float4(to_tf32(r[0]), to_tf32(r[4]), to_tf32(r[8]), to_tf32(r[12]));
            ((float4*)d_whhf)[id] = q;
        }
    }
}

// ---------------- init: h0, x0, zero rows ----------------
__global__ void init_kernel(const float* __restrict__ z, const float* __restrict__ labels,
                            const float* __restrict__ emb, const float* __restrict__ fcw,
                            const float* __restrict__ fcb, float* __restrict__ out) {
    int64_t i = (int64_t)blockIdx.x * blockDim.x + threadIdx.x;
    int64_t stride = (int64_t)gridDim.x * blockDim.x;
    const int64_t NH0 = 32768;
    const int64_t NZ  = 65536;
    const int64_t NX  = 81920;
    const int64_t NP  = NX + (int64_t)OUT_P_STRIDE;
    for (; i < NP; i += stride) {
        if (i < NH0) {
            int b = (int)(i >> 9), j = (int)(i & 511);
            float v = (j < 64) ? (1.f - labels[b]) * fcw[j] + fcb[j]
                               : z[b * 448 + (j - 64)];
            d_h[0][i] = v; out[i] = v;
            d_hfrag[0][frag_idx(b, j, 64)] = to_tf32(v);
        } else if (i < NZ) {
            out[i] = 0.f;
        } else if (i < NX) {
            int l = (int)(i - NZ); int b = l >> 8, c = l & 255;
            d_xfrag[frag_idx(b, c, 32)] = to_tf32(emb[2 * EMBED + c]);   // IDX_SOS = 2
        } else {
            out[PRED_OFF + (i - NX)] = 0.f;
        }
    }
}

// ---------------- GRU cell: K-split over 8 warps ----------------
// warps 0-3 (half 0): gi (kp 0..15) + gh (kp 0..7)   = 24 iters
// warps 4-7 (half 1): gh (kp 8..31)                  = 24 iters
__global__ __launch_bounds__(256) void gru_kernel(int cur,
        const float* __restrict__ bih, const float* __restrict__ bhh,
        float* __restrict__ outh) {
    __shared__ float sAcc[4][32][12];
    const int nxt = cur ^ 1;
    int tid = threadIdx.x, lane = tid & 31, warp = tid >> 5;
    int mt = warp & 3, half = warp >> 2;
    int g = lane >> 2, tig = lane & 3;
    int jb = blockIdx.x;
    int j0 = jb * 8;
    int m0 = mt * 16;
    uint64_t pol = mk_evict_last_policy();

    float acc[6][4];
    #pragma unroll
    for (int a = 0; a < 6; a++)
        #pragma unroll
        for (int b = 0; b < 4; b++) acc[a][b] = 0.f;

    const float4* Ax = (const float4*)d_xfrag + mt * 1024 + lane;
    const float4* Ah = (const float4*)d_hfrag[cur] + mt * 2048 + lane;
    const float4* Bi = (const float4*)d_wihf + jb * 512 + lane;    // gate stride 32768
    const float4* Bh = (const float4*)d_whhf + jb * 1024 + lane;   // gate stride 65536

    if (half == 0) {
        // gi = x @ w_ih^T  (kp 0..15), double-buffered
        float4 a0 = __ldg(&Ax[0]), a1 = __ldg(&Ax[32]);
        float4 c0 = ldgEL(&Bi[0], pol), c1 = ldgEL(&Bi[32768], pol), c2 = ldgEL(&Bi[65536], pol);
        #pragma unroll 1
        for (int kp = 0; kp < 16; kp += 2) {
            float4 a0n = __ldg(&Ax[(2*kp+2)*32]), a1n = __ldg(&Ax[(2*kp+3)*32]);
            float4 n0 = ldgEL(&Bi[(kp+1)*32], pol);
            float4 n1 = ldgEL(&Bi[32768 + (kp+1)*32], pol);
            float4 n2 = ldgEL(&Bi[65536 + (kp+1)*32], pol);
            mma8(acc[0], a0, c0.x, c0.y); mma8(acc[0], a1, c0.z, c0.w);
            mma8(acc[1], a0, c1.x, c1.y); mma8(acc[1], a1, c1.z, c1.w);
            mma8(acc[2], a0, c2.x, c2.y); mma8(acc[2], a1, c2.z, c2.w);
            int kp2 = (kp + 2 < 16) ? kp + 2 : 15;
            a0 = __ldg(&Ax[(2*kp2)*32]); a1 = __ldg(&Ax[(2*kp2+1)*32]);
            c0 = ldgEL(&Bi[kp2*32], pol);
            c1 = ldgEL(&Bi[32768 + kp2*32], pol);
            c2 = ldgEL(&Bi[65536 + kp2*32], pol);
            mma8(acc[0], a0n, n0.x, n0.y); mma8(acc[0], a1n, n0.z, n0.w);
            mma8(acc[1], a0n, n1.x, n1.y); mma8(acc[1], a1n, n1.z, n1.w);
            mma8(acc[2], a0n, n2.x, n2.y); mma8(acc[2], a1n, n2.z, n2.w);
        }
    }
    {
        // gh = h @ w_hh^T, half 0: kp 0..7, half 1: kp 8..31
        const int kpBeg = (half == 0) ? 0 : 8;
        const int kpEnd = (half == 0) ? 8 : 32;
        float4 a0 = __ldg(&Ah[(2*kpBeg)*32]), a1 = __ldg(&Ah[(2*kpBeg+1)*32]);
        float4 c0 = ldgEL(&Bh[kpBeg*32], pol);
        float4 c1 = ldgEL(&Bh[65536 + kpBeg*32], pol);
        float4 c2 = ldgEL(&Bh[131072 + kpBeg*32], pol);
        #pragma unroll 1
        for (int kp = kpBeg; kp < kpEnd; kp += 2) {
            float4 a0n = __ldg(&Ah[(2*kp+2)*32]), a1n = __ldg(&Ah[(2*kp+3)*32]);
            float4 n0 = ldgEL(&Bh[(kp+1)*32], pol);
            float4 n1 = ldgEL(&Bh[65536 + (kp+1)*32], pol);
            float4 n2 = ldgEL(&Bh[131072 + (kp+1)*32], pol);
            mma8(acc[3], a0, c0.x, c0.y); mma8(acc[3], a1, c0.z, c0.w);
            mma8(acc[4], a0, c1.x, c1.y); mma8(acc[4], a1, c1.z, c1.w);
            mma8(acc[5], a0, c2.x, c2.y); mma8(acc[5], a1, c2.z, c2.w);
            int kp2 = (kp + 2 < kpEnd) ? kp + 2 : kpEnd - 1;
            a0 = __ldg(&Ah[(2*kp2)*32]); a1 = __ldg(&Ah[(2*kp2+1)*32]);
            c0 = ldgEL(&Bh[kp2*32], pol);
            c1 = ldgEL(&Bh[65536 + kp2*32], pol);
            c2 = ldgEL(&Bh[131072 + kp2*32], pol);
            mma8(acc[3], a0n, n0.x, n0.y); mma8(acc[3], a1n, n0.z, n0.w);
            mma8(acc[4], a0n, n1.x, n1.y); mma8(acc[4], a1n, n1.z, n1.w);
            mma8(acc[5], a0n, n2.x, n2.y); mma8(acc[5], a1n, n2.z, n2.w);
        }
    }
    // half 1 publishes its gh partials
    if (half == 1) {
        #pragma unroll
        for (int a = 0; a < 3; a++)
            #pragma unroll
            for (int b = 0; b < 4; b++) sAcc[mt][lane][a * 4 + b] = acc[3 + a][b];
    }
    __syncthreads();
    if (half == 0) {
        #pragma unroll
        for (int a = 0; a < 3; a++)
            #pragma unroll
            for (int b = 0; b < 4; b++) acc[3 + a][b] += sAcc[mt][lane][a * 4 + b];
        const float* hp = d_h[cur];
        float* hn = d_h[nxt];
        float* hf = d_hfrag[nxt];
        #pragma unroll
        for (int idx = 0; idx < 4; idx++) {
            int m = m0 + g + ((idx & 2) ? 8 : 0);
            int j = j0 + 2 * tig + (idx & 1);
            float ir  = acc[0][idx] + bih[j];            float hr  = acc[3][idx] + bhh[j];
            float iz  = acc[1][idx] + bih[DIMH + j];     float hz  = acc[4][idx] + bhh[DIMH + j];
            float inn = acc[2][idx] + bih[2*DIMH + j];   float hnn = acc[5][idx] + bhh[2*DIMH + j];
            float r  = 1.f / (1.f + expf(-(ir + hr)));
            float zg = 1.f / (1.f + expf(-(iz + hz)));
            float nn = tanhf(inn + r * hnn);
            float hv = (1.f - zg) * nn + zg * hp[m * DIMH + j];
            hn[m * DIMH + j] = hv;
            __stcs(&outh[m * DIMH + j], hv);
            hf[frag_idx(m, j, 64)] = to_tf32(hv);
        }
    }
}

// ---------------- pred + softmax partials per 128-vocab block ----------------
// block = 1024 threads = 32 warps: mt = warp&3 (M tile), nh = warp>>2 (16-col vocab slice)
__global__ __launch_bounds__(1024, 1) void pred_kernel(int parity,
        const float* __restrict__ gum, const float* __restrict__ outb,
        float* __restrict__ predout) {
    __shared__ __align__(16) float sEf[4 * 16 * 32 * 4];   // e in A-fragment layout, 32KB
    __shared__ float sS2[64][8];
    int tid = threadIdx.x, lane = tid & 31, warp = tid >> 5;
    int g = lane >> 2, tig = lane & 3;
    int mt = warp & 3, nh = warp >> 2;     // nh in 0..7
    int vb = blockIdx.x;
    uint64_t pol = mk_evict_last_policy();

    // ---- phase 1: pred = h @ out_w^T  (M=64, N per warp = 16, K=512) ----
    float pacc[2][4];
    #pragma unroll
    for (int a = 0; a < 2; a++)
        #pragma unroll
        for (int b = 0; b < 4; b++) pacc[a][b] = 0.f;

    const float4* Af = (const float4*)d_hfrag[parity] + mt * 2048 + lane;
    // global ntG = nh*2 + nt' (0..15); nhOld = nh>>2, ntOld0 = (nh&3)*2
    const float4* Bf = (const float4*)d_outwf
        + (vb * 2 + (nh >> 2)) * 8192 + ((nh & 3) * 2) * 1024 + lane;

    {
        float4 a0 = __ldg(&Af[0]), a1 = __ldg(&Af[32]);
        float4 bc0 = ldgEL(&Bf[0], pol), bc1 = ldgEL(&Bf[1024], pol);
        #pragma unroll 1
        for (int kp = 0; kp < 32; kp += 2) {
            float4 a0n = __ldg(&Af[(2*kp+2)*32]), a1n = __ldg(&Af[(2*kp+3)*32]);
            float4 bn0 = ldgEL(&Bf[(kp+1)*32], pol);
            float4 bn1 = ldgEL(&Bf[1024 + (kp+1)*32], pol);
            mma8(pacc[0], a0, bc0.x, bc0.y); mma8(pacc[0], a1, bc0.z, bc0.w);
            mma8(pacc[1], a0, bc1.x, bc1.y); mma8(pacc[1], a1, bc1.z, bc1.w);
            int kp2 = (kp + 2 < 32) ? kp + 2 : 31;
            a0 = __ldg(&Af[(2*kp2)*32]); a1 = __ldg(&Af[(2*kp2+1)*32]);
            bc0 = ldgEL(&Bf[kp2*32], pol);
            bc1 = ldgEL(&Bf[1024 + kp2*32], pol);
            mma8(pacc[0], a0n, bn0.x, bn0.y); mma8(pacc[0], a1n, bn0.z, bn0.w);
            mma8(pacc[1], a0n, bn1.x, bn1.y); mma8(pacc[1], a1n, bn1.z, bn1.w);
        }
    }

    // ---- epilogue: write pred (streaming), e = exp(pred + gumbel), stash e-frags ----
    int rA = mt * 16 + g, rB = rA + 8;
    float slo = 0.f, shi = 0.f;
    #pragma unroll
    for (int nt = 0; nt < 2; nt++) {
        int vcol = nh * 16 + nt * 8 + 2 * tig;
        int vg = vb * 128 + vcol;
        float ob0 = __ldg(&outb[vg]), ob1 = __ldg(&outb[vg + 1]);
        float p00 = pacc[nt][0] + ob0, p01 = pacc[nt][1] + ob1;
        float p10 = pacc[nt][2] + ob0, p11 = pacc[nt][3] + ob1;
        __stcs((float2*)&predout[rA * VOCAB + vg], make_float2(p00, p01));
        __stcs((float2*)&predout[rB * VOCAB + vg], make_float2(p10, p11));
        float2 gA = __ldcs((const float2*)&gum[rA * VOCAB + vg]);
        float2 gB = __ldcs((const float2*)&gum[rB * VOCAB + vg]);
        float e00 = __expf(p00 + gA.x), e01 = __expf(p01 + gA.y);
        float e10 = __expf(p10 + gB.x), e11 = __expf(p11 + gB.y);
        slo += e00 + e01; shi += e10 + e11;
        // scatter into A-fragment layout (k8 dim = 16 for K=128)
        int k8 = nh * 2 + nt;
        int kc0 = 2 * tig, kc1 = 2 * tig + 1;
        int lane0 = (g << 2) | (kc0 & 3), slot0h = (kc0 >= 4) ? 2 : 0;
        int lane1 = (g << 2) | (kc1 & 3), slot1h = (kc1 >= 4) ? 2 : 0;
        float* baseA0 = &sEf[((mt * 16 + k8) * 32 + lane0) * 4];
        float* baseA1 = &sEf[((mt * 16 + k8) * 32 + lane1) * 4];
        baseA0[slot0h + 0] = to_tf32(e00);
        baseA1[slot1h + 0] = to_tf32(e01);
        baseA0[slot0h + 1] = to_tf32(e10);
        baseA1[slot1h + 1] = to_tf32(e11);
    }
    slo += __shfl_down_sync(0xffffffffu, slo, 1);
    slo += __shfl_down_sync(0xffffffffu, slo, 2);
    shi += __shfl_down_sync(0xffffffffu, shi, 1);
    shi += __shfl_down_sync(0xffffffffu, shi, 2);
    if (tig == 0) {                     // unique (row, nh) writer: deterministic
        sS2[rA][nh] = slo;
        sS2[rB][nh] = shi;
    }
    __syncthreads();
    if (tid < 64) {
        float s = 0.f;
        #pragma unroll
        for (int q = 0; q < 8; q++) s += sS2[tid][q];
        d_pS[vb * 64 + tid] = s;
    }

    // ---- phase 3: partial E = e @ emb_chunk  (M=64, N per warp = 32, K=128) ----
    const float4* sE4 = (const float4*)sEf + mt * 512 + lane;
    // global ntG = nh*4 + t (0..31); nhOld = nh>>2, ntOld = (nh&3)*4 + t
    const float4* Ef = (const float4*)d_embf
        + (vb * 2 + (nh >> 2)) * 4096 + ((nh & 3) * 4) * 256 + lane;
    float* pEblk = d_pE + vb * (BATCH * EMBED);

    float eacc[4][4];
    #pragma unroll
    for (int a = 0; a < 4; a++)
        #pragma unroll
        for (int b = 0; b < 4; b++) eacc[a][b] = 0.f;

    #pragma unroll 2
    for (int kp = 0; kp < 8; kp++) {
        float4 a0 = sE4[(2 * kp) * 32];
        float4 a1 = sE4[(2 * kp + 1) * 32];
        #pragma unroll
        for (int t = 0; t < 4; t++) {
            float4 b = ldgEL(&Ef[(t * 8 + kp) * 32], pol);
            mma8(eacc[t], a0, b.x, b.y);
            mma8(eacc[t], a1, b.z, b.w);
        }
    }
    #pragma unroll
    for (int t = 0; t < 4; t++) {
        int c = (nh * 4 + t) * 8 + 2 * tig;
        __stcs((float2*)&pEblk[rA * EMBED + c], make_float2(eacc[t][0], eacc[t][1]));
        __stcs((float2*)&pEblk[rB * EMBED + c], make_float2(eacc[t][2], eacc[t][3]));
    }
}

// ---------------- reduce partials -> x_next (fragment layout) ----------------
__global__ __launch_bounds__(64) void reduce_kernel() {
    __shared__ float sred[64];
    int b = blockIdx.x, tid = threadIdx.x;
    float s = 0.f;
    for (int k = tid; k < NPB; k += 64) s += d_pS[k * 64 + b];
    sred[tid] = s;
    __syncthreads();
    #pragma unroll
    for (int off = 32; off > 0; off >>= 1) {
        if (tid < off) sred[tid] += sred[tid + off];
        __syncthreads();
    }
    float sinv = 1.f / (GAMMA * sred[0]);
    int c = blockIdx.y * 64 + tid;
    float acc = 0.f;
    const float* p = d_pE + b * EMBED + c;
    #pragma unroll 25
    for (int k = 0; k < NPB; k++) acc += __ldcs(&p[k * (BATCH * EMBED)]);
    d_xfrag[frag_idx(b, c, 32)] = to_tf32(acc * sinv);
}

// ---------------- launch ----------------
extern "C" void kernel_launch(void* const* d_in, const int* in_sizes, int n_in,
                              void* d_out, int out_size) {
    const float* z      = (const float*)d_in[0];
    const float* labels = (const float*)d_in[1];
    // d_in[2] src, d_in[3] src_len: unused by the transfered=True path
    const float* gum    = (const float*)d_in[4];
    const float* emb    = (const float*)d_in[5];
    const float* fcw    = (const float*)d_in[6];
    const float* fcb    = (const float*)d_in[7];
    const float* wih    = (const float*)d_in[8];
    const float* whh    = (const float*)d_in[9];
    const float* bih    = (const float*)d_in[10];
    const float* bhh    = (const float*)d_in[11];
    const float* outw   = (const float*)d_in[12];
    const float* outb   = (const float*)d_in[13];
    float* out = (float*)d_out;

    prep_kernel<<<2048, 256>>>(outw, emb, wih, whh);
    init_kernel<<<1024, 256>>>(z, labels, emb, fcw, fcb, out);

    for (int i = 0; i < TSTEPS; i++) {
        int cur = i & 1, nxt = cur ^ 1;
        gru_kernel<<<64, 256>>>(cur, bih, bhh, out + (int64_t)(2 + i) * OUT_H_STRIDE);
        pred_kernel<<<NPB, 1024>>>(nxt, gum + (int64_t)i * OUT_P_STRIDE,
                                   outb, out + PRED_OFF + (int64_t)(i + 1) * OUT_P_STRIDE);
        if (i < TSTEPS - 1) reduce_kernel<<<dim3(64, 4), 64>>>();
    }
}

// round 9
// speedup vs baseline: 2.8886x; 1.1950x over previous
#include <cuda_runtime.h>
#include <cuda_fp16.h>
#include <cstdint>

#define BATCH 64
#define VOCAB 16000
#define EMBED 256
#define DIMH  512
#define G3    1536
#define TSTEPS 63
#define GAMMA 0.1f
#define VC    128
#define NPB   125   // pred blocks = VOCAB / VC
#define EBIAS 10.0f

#define OUT_H_STRIDE (BATCH*DIMH)     // 32768
#define OUT_P_STRIDE (BATCH*VOCAB)    // 1024000
#define PRED_OFF (65*OUT_H_STRIDE)    // 2129920

// ---------------- scratch (device globals; no allocation) ----------------
__device__ __align__(16) float d_h[2][BATCH*DIMH];      // fp32 hidden state (row-major, ping-pong)
__device__ uint4 d_hfrag4[2][4096];    // fp16 h, A-frag layout [mt4][k16_32][lane32], 64KB each
__device__ uint4 d_xfrag4[2048];       // fp16 x, A-frag layout [mt4][k16_16][lane32], 32KB
__device__ __align__(16) float d_pE[NPB*BATCH*EMBED];   // partial E sums (fp32)
__device__ float d_pS[NPB*BATCH];                       // partial softmax denominators
// B-operand fp16 fragment layouts (precomputed once)
__device__ uint4 d_outwf4[1024000];   // [vb125][nt16][kq16][lane32]  (16 MB)
__device__ uint4 d_embf4[512000];     // [vb125][nt32][kq4][lane32]   (8 MB)
__device__ uint4 d_wihf4[49152];      // [gate3][jb64][kq8][lane32]
__device__ uint4 d_whhf4[98304];      // [gate3][jb64][kq16][lane32]

// ---------------- helpers ----------------
__device__ __forceinline__ unsigned f2h2(float lo, float hi) {
    __half2 h = __floats2half2_rn(lo, hi);
    return *(unsigned*)&h;
}

// D(fp32) += A(fp16 16x16) * B(fp16 16x8)
__device__ __forceinline__ void mma16(float* c, uint4 a, unsigned b0, unsigned b1) {
    asm volatile(
        "mma.sync.aligned.m16n8k16.row.col.f32.f16.f16.f32 "
        "{%0,%1,%2,%3}, {%4,%5,%6,%7}, {%8,%9}, {%0,%1,%2,%3};\n"
        : "+f"(c[0]), "+f"(c[1]), "+f"(c[2]), "+f"(c[3])
        : "r"(a.x), "r"(a.y), "r"(a.z), "r"(a.w), "r"(b0), "r"(b1));
}

// half index of element (row m in 0..63, col k) within A-frag array of K16dim chunks
__device__ __forceinline__ int frag_h_idx(int m, int k, int K16dim) {
    int mt = m >> 4, mr = m & 15, k16 = k >> 4, kc = k & 15;
    int lane = ((mr & 7) << 2) | ((kc & 7) >> 1);
    int reg = ((mr >= 8) ? 1 : 0) | ((kc >= 8) ? 2 : 0);
    return (((mt * K16dim + k16) * 32 + lane) << 3) + (reg << 1) + (kc & 1);
}

// ---------------- prep: build fp16 fragment-layout weights ----------------
__global__ void prep_kernel(const float* __restrict__ outw, const float* __restrict__ emb,
                            const float* __restrict__ wih,  const float* __restrict__ whh) {
    const int N1 = 1024000;            // outwf4
    const int N2 = N1 + 512000;        // embf4
    const int N3 = N2 + 49152;         // wihf4
    const int N4 = N3 + 98304;         // whhf4
    for (int gid = blockIdx.x * blockDim.x + threadIdx.x; gid < N4;
         gid += gridDim.x * blockDim.x) {
        uint4 q;
        if (gid < N1) {
            int lane = gid & 31, kq = (gid >> 5) & 15, nt = (gid >> 9) & 15, vb = gid >> 13;
            int g = lane >> 2, tig = lane & 3;
            int n = vb * 128 + nt * 8 + g;
            const float* r = outw + n * DIMH + kq * 32 + 2 * tig;
            q.x = f2h2(r[0], r[1]);   q.y = f2h2(r[8], r[9]);
            q.z = f2h2(r[16], r[17]); q.w = f2h2(r[24], r[25]);
            d_outwf4[gid] = q;
        } else if (gid < N2) {
            int id = gid - N1;
            int lane = id & 31, kq = (id >> 5) & 3, nt = (id >> 7) & 31, vb = id >> 12;
            int g = lane >> 2, tig = lane & 3;
            int n = nt * 8 + g;
            const float* r = emb + (int64_t)(vb * 128 + kq * 32 + 2 * tig) * EMBED + n;
            q.x = f2h2(r[0], r[EMBED]);
            q.y = f2h2(r[8 * EMBED], r[9 * EMBED]);
            q.z = f2h2(r[16 * EMBED], r[17 * EMBED]);
            q.w = f2h2(r[24 * EMBED], r[25 * EMBED]);
            d_embf4[id] = q;
        } else if (gid < N3) {
            int id = gid - N2;
            int lane = id & 31, kq = (id >> 5) & 7, jb = (id >> 8) & 63, gate = id >> 14;
            int g = lane >> 2, tig = lane & 3;
            int row = gate * DIMH + jb * 8 + g;
            const float* r = wih + row * EMBED + kq * 32 + 2 * tig;
            q.x = f2h2(r[0], r[1]);   q.y = f2h2(r[8], r[9]);
            q.z = f2h2(r[16], r[17]); q.w = f2h2(r[24], r[25]);
            d_wihf4[id] = q;
        } else {
            int id = gid - N3;
            int lane = id & 31, kq = (id >> 5) & 15, jb = (id >> 9) & 63, gate = id >> 15;
            int g = lane >> 2, tig = lane & 3;
            int row = gate * DIMH + jb * 8 + g;
            const float* r = whh + row * DIMH + kq * 32 + 2 * tig;
            q.x = f2h2(r[0], r[1]);   q.y = f2h2(r[8], r[9]);
            q.z = f2h2(r[16], r[17]); q.w = f2h2(r[24], r[25]);
            d_whhf4[id] = q;
        }
    }
}

// ---------------- init: h0, x0, zero rows ----------------
__global__ void init_kernel(const float* __restrict__ z, const float* __restrict__ labels,
                            const float* __restrict__ emb, const float* __restrict__ fcw,
                            const float* __restrict__ fcb, float* __restrict__ out) {
    __half* hfh = (__half*)d_hfrag4[0];
    __half* xfh = (__half*)d_xfrag4;
    int64_t i = (int64_t)blockIdx.x * blockDim.x + threadIdx.x;
    int64_t stride = (int64_t)gridDim.x * blockDim.x;
    const int64_t NH0 = 32768;
    const int64_t NZ  = 65536;
    const int64_t NX  = 81920;
    const int64_t NP  = NX + (int64_t)OUT_P_STRIDE;
    for (; i < NP; i += stride) {
        if (i < NH0) {
            int b = (int)(i >> 9), j = (int)(i & 511);
            float v = (j < 64) ? (1.f - labels[b]) * fcw[j] + fcb[j]
                               : z[b * 448 + (j - 64)];
            d_h[0][i] = v; out[i] = v;
            hfh[frag_h_idx(b, j, 32)] = __float2half_rn(v);
        } else if (i < NZ) {
            out[i] = 0.f;
        } else if (i < NX) {
            int l = (int)(i - NZ); int b = l >> 8, c = l & 255;
            xfh[frag_h_idx(b, c, 16)] = __float2half_rn(emb[2 * EMBED + c]);  // IDX_SOS = 2
        } else {
            out[PRED_OFF + (i - NX)] = 0.f;
        }
    }
}

// ---------------- GRU cell: K-split over 8 warps ----------------
// half 0: gi (kq 0..7, K=32 each) + gh (kq 0..3) = 12 iters
// half 1: gh (kq 4..15)                          = 12 iters
__global__ __launch_bounds__(256) void gru_kernel(int cur,
        const float* __restrict__ bih, const float* __restrict__ bhh,
        float* __restrict__ outh) {
    __shared__ float sAcc[4][32][12];
    const int nxt = cur ^ 1;
    int tid = threadIdx.x, lane = tid & 31, warp = tid >> 5;
    int mt = warp & 3, half = warp >> 2;
    int g = lane >> 2, tig = lane & 3;
    int jb = blockIdx.x;
    int j0 = jb * 8;
    int m0 = mt * 16;

    float acc[6][4];
    #pragma unroll
    for (int a = 0; a < 6; a++)
        #pragma unroll
        for (int b = 0; b < 4; b++) acc[a][b] = 0.f;

    const uint4* Ax = d_xfrag4 + mt * 512 + lane;          // k16 stride 32
    const uint4* Ah = d_hfrag4[cur] + mt * 1024 + lane;
    const uint4* Bi = d_wihf4 + jb * 256 + lane;           // gate stride 16384, kq stride 32
    const uint4* Bh = d_whhf4 + jb * 512 + lane;           // gate stride 32768, kq stride 32

    if (half == 0) {
        #pragma unroll 4
        for (int kq = 0; kq < 8; kq++) {
            uint4 a0 = __ldg(&Ax[(2*kq)*32]), a1 = __ldg(&Ax[(2*kq+1)*32]);
            uint4 b0 = __ldg(&Bi[kq*32]);
            uint4 b1 = __ldg(&Bi[16384 + kq*32]);
            uint4 b2 = __ldg(&Bi[32768 + kq*32]);
            mma16(acc[0], a0, b0.x, b0.y); mma16(acc[0], a1, b0.z, b0.w);
            mma16(acc[1], a0, b1.x, b1.y); mma16(acc[1], a1, b1.z, b1.w);
            mma16(acc[2], a0, b2.x, b2.y); mma16(acc[2], a1, b2.z, b2.w);
        }
    }
    {
        const int kpBeg = (half == 0) ? 0 : 4;
        const int kpEnd = (half == 0) ? 4 : 16;
        #pragma unroll 4
        for (int kq = kpBeg; kq < kpEnd; kq++) {
            uint4 a0 = __ldg(&Ah[(2*kq)*32]), a1 = __ldg(&Ah[(2*kq+1)*32]);
            uint4 b0 = __ldg(&Bh[kq*32]);
            uint4 b1 = __ldg(&Bh[32768 + kq*32]);
            uint4 b2 = __ldg(&Bh[65536 + kq*32]);
            mma16(acc[3], a0, b0.x, b0.y); mma16(acc[3], a1, b0.z, b0.w);
            mma16(acc[4], a0, b1.x, b1.y); mma16(acc[4], a1, b1.z, b1.w);
            mma16(acc[5], a0, b2.x, b2.y); mma16(acc[5], a1, b2.z, b2.w);
        }
    }
    if (half == 1) {
        #pragma unroll
        for (int a = 0; a < 3; a++)
            #pragma unroll
            for (int b = 0; b < 4; b++) sAcc[mt][lane][a * 4 + b] = acc[3 + a][b];
    }
    __syncthreads();
    if (half == 0) {
        #pragma unroll
        for (int a = 0; a < 3; a++)
            #pragma unroll
            for (int b = 0; b < 4; b++) acc[3 + a][b] += sAcc[mt][lane][a * 4 + b];
        const float* hp = d_h[cur];
        float* hn = d_h[nxt];
        __half* hf = (__half*)d_hfrag4[nxt];
        #pragma unroll
        for (int idx = 0; idx < 4; idx++) {
            int m = m0 + g + ((idx & 2) ? 8 : 0);
            int j = j0 + 2 * tig + (idx & 1);
            float ir  = acc[0][idx] + bih[j];            float hr  = acc[3][idx] + bhh[j];
            float iz  = acc[1][idx] + bih[DIMH + j];     float hz  = acc[4][idx] + bhh[DIMH + j];
            float inn = acc[2][idx] + bih[2*DIMH + j];   float hnn = acc[5][idx] + bhh[2*DIMH + j];
            float r  = 1.f / (1.f + expf(-(ir + hr)));
            float zg = 1.f / (1.f + expf(-(iz + hz)));
            float nn = tanhf(inn + r * hnn);
            float hv = (1.f - zg) * nn + zg * hp[m * DIMH + j];
            hn[m * DIMH + j] = hv;
            __stcs(&outh[m * DIMH + j], hv);
            hf[frag_h_idx(m, j, 32)] = __float2half_rn(hv);
        }
    }
}

// ---------------- pred + softmax partials per 128-vocab block ----------------
// block = 1024 threads = 32 warps: mt = warp&3 (M tile), nh = warp>>2 (16-col vocab slice)
__global__ __launch_bounds__(1024, 1) void pred_kernel(int parity,
        const float* __restrict__ gum, const float* __restrict__ outb,
        float* __restrict__ predout) {
    __shared__ __align__(16) uint4 sEf4[4 * 8 * 32];   // e fp16 A-frag layout, 16KB
    __shared__ float sS2[64][8];
    int tid = threadIdx.x, lane = tid & 31, warp = tid >> 5;
    int g = lane >> 2, tig = lane & 3;
    int mt = warp & 3, nh = warp >> 2;     // nh in 0..7
    int vb = blockIdx.x;

    // ---- phase 1: pred = h @ out_w^T  (M=64, N per warp = 16, K=512) ----
    float pacc[2][4];
    #pragma unroll
    for (int a = 0; a < 2; a++)
        #pragma unroll
        for (int b = 0; b < 4; b++) pacc[a][b] = 0.f;

    const uint4* Af = d_hfrag4[parity] + mt * 1024 + lane;
    const uint4* Bf = d_outwf4 + vb * 8192 + nh * 1024 + lane;  // nt stride 512, kq stride 32

    {
        uint4 a0 = __ldg(&Af[0]), a1 = __ldg(&Af[32]);
        uint4 c0 = __ldg(&Bf[0]), c1 = __ldg(&Bf[512]);
        #pragma unroll 1
        for (int kq = 0; kq < 16; kq++) {
            int kqn = (kq + 1 < 16) ? kq + 1 : 15;
            uint4 a0n = __ldg(&Af[(2*kqn)*32]), a1n = __ldg(&Af[(2*kqn+1)*32]);
            uint4 n0 = __ldg(&Bf[kqn*32]), n1 = __ldg(&Bf[512 + kqn*32]);
            mma16(pacc[0], a0, c0.x, c0.y); mma16(pacc[0], a1, c0.z, c0.w);
            mma16(pacc[1], a0, c1.x, c1.y); mma16(pacc[1], a1, c1.z, c1.w);
            a0 = a0n; a1 = a1n; c0 = n0; c1 = n1;
        }
    }

    // ---- epilogue: write pred (fp32), e = exp(pred + g - EBIAS), stash fp16 e-frags ----
    int rA = mt * 16 + g, rB = rA + 8;
    unsigned* sEfu = (unsigned*)sEf4;
    float slo = 0.f, shi = 0.f;
    #pragma unroll
    for (int nt = 0; nt < 2; nt++) {
        int vcol = nh * 16 + nt * 8 + 2 * tig;
        int vg = vb * 128 + vcol;
        float ob0 = __ldg(&outb[vg]), ob1 = __ldg(&outb[vg + 1]);
        float p00 = pacc[nt][0] + ob0, p01 = pacc[nt][1] + ob1;
        float p10 = pacc[nt][2] + ob0, p11 = pacc[nt][3] + ob1;
        __stcs((float2*)&predout[rA * VOCAB + vg], make_float2(p00, p01));
        __stcs((float2*)&predout[rB * VOCAB + vg], make_float2(p10, p11));
        float2 gA = __ldcs((const float2*)&gum[rA * VOCAB + vg]);
        float2 gB = __ldcs((const float2*)&gum[rB * VOCAB + vg]);
        unsigned eA = f2h2(__expf(p00 + gA.x - EBIAS), __expf(p01 + gA.y - EBIAS));
        unsigned eB = f2h2(__expf(p10 + gB.x - EBIAS), __expf(p11 + gB.y - EBIAS));
        // S from the rounded values (consistent with the fp16 GEMM numerator)
        float2 fA = __half22float2(*(__half2*)&eA);
        float2 fB = __half22float2(*(__half2*)&eB);
        slo += fA.x + fA.y; shi += fB.x + fB.y;
        int idx32 = (((mt * 8 + nh) * 32 + lane) << 2) + nt * 2;
        sEfu[idx32] = eA;
        sEfu[idx32 + 1] = eB;
    }
    slo += __shfl_down_sync(0xffffffffu, slo, 1);
    slo += __shfl_down_sync(0xffffffffu, slo, 2);
    shi += __shfl_down_sync(0xffffffffu, shi, 1);
    shi += __shfl_down_sync(0xffffffffu, shi, 2);
    if (tig == 0) {
        sS2[rA][nh] = slo;
        sS2[rB][nh] = shi;
    }
    __syncthreads();
    if (tid < 64) {
        float s = 0.f;
        #pragma unroll
        for (int q = 0; q < 8; q++) s += sS2[tid][q];
        d_pS[vb * 64 + tid] = s;
    }

    // ---- phase 3: partial E = e @ emb_chunk  (M=64, N per warp = 32, K=128) ----
    const uint4* sE4 = sEf4 + mt * 256 + lane;                      // k16 stride 32
    const uint4* Ef = d_embf4 + vb * 4096 + (nh * 4) * 128 + lane;  // t stride 128, kq stride 32
    float* pEblk = d_pE + vb * (BATCH * EMBED);

    float eacc[4][4];
    #pragma unroll
    for (int a = 0; a < 4; a++)
        #pragma unroll
        for (int b = 0; b < 4; b++) eacc[a][b] = 0.f;

    #pragma unroll
    for (int kq = 0; kq < 4; kq++) {
        uint4 a0 = sE4[(2 * kq) * 32];
        uint4 a1 = sE4[(2 * kq + 1) * 32];
        #pragma unroll
        for (int t = 0; t < 4; t++) {
            uint4 be = __ldg(&Ef[t * 128 + kq * 32]);
            mma16(eacc[t], a0, be.x, be.y);
            mma16(eacc[t], a1, be.z, be.w);
        }
    }
    #pragma unroll
    for (int t = 0; t < 4; t++) {
        int c = (nh * 4 + t) * 8 + 2 * tig;
        __stcs((float2*)&pEblk[rA * EMBED + c], make_float2(eacc[t][0], eacc[t][1]));
        __stcs((float2*)&pEblk[rB * EMBED + c], make_float2(eacc[t][2], eacc[t][3]));
    }
}

// ---------------- reduce partials -> x_next (fp16 fragment layout) ----------------
__global__ __launch_bounds__(64) void reduce_kernel() {
    __shared__ float sred[64];
    int b = blockIdx.x, tid = threadIdx.x;
    float s = 0.f;
    for (int k = tid; k < NPB; k += 64) s += d_pS[k * 64 + b];
    sred[tid] = s;
    __syncthreads();
    #pragma unroll
    for (int off = 32; off > 0; off >>= 1) {
        if (tid < off) sred[tid] += sred[tid + off];
        __syncthreads();
    }
    float sinv = 1.f / (GAMMA * sred[0]);
    int c = blockIdx.y * 64 + tid;
    float acc = 0.f;
    const float* p = d_pE + b * EMBED + c;
    #pragma unroll 25
    for (int k = 0; k < NPB; k++) acc += __ldcs(&p[k * (BATCH * EMBED)]);
    ((__half*)d_xfrag4)[frag_h_idx(b, c, 16)] = __float2half_rn(acc * sinv);
}

// ---------------- launch ----------------
extern "C" void kernel_launch(void* const* d_in, const int* in_sizes, int n_in,
                              void* d_out, int out_size) {
    const float* z      = (const float*)d_in[0];
    const float* labels = (const float*)d_in[1];
    // d_in[2] src, d_in[3] src_len: unused by the transfered=True path
    const float* gum    = (const float*)d_in[4];
    const float* emb    = (const float*)d_in[5];
    const float* fcw    = (const float*)d_in[6];
    const float* fcb    = (const float*)d_in[7];
    const float* wih    = (const float*)d_in[8];
    const float* whh    = (const float*)d_in[9];
    const float* bih    = (const float*)d_in[10];
    const float* bhh    = (const float*)d_in[11];
    const float* outw   = (const float*)d_in[12];
    const float* outb   = (const float*)d_in[13];
    float* out = (float*)d_out;

    prep_kernel<<<2048, 256>>>(outw, emb, wih, whh);
    init_kernel<<<1024, 256>>>(z, labels, emb, fcw, fcb, out);

    for (int i = 0; i < TSTEPS; i++) {
        int cur = i & 1, nxt = cur ^ 1;
        gru_kernel<<<64, 256>>>(cur, bih, bhh, out + (int64_t)(2 + i) * OUT_H_STRIDE);
        pred_kernel<<<NPB, 1024>>>(nxt, gum + (int64_t)i * OUT_P_STRIDE,
                                   outb, out + PRED_OFF + (int64_t)(i + 1) * OUT_P_STRIDE);
        if (i < TSTEPS - 1) reduce_kernel<<<dim3(64, 4), 64>>>();
    }
}